// round 15
// baseline (speedup 1.0000x reference)
#include <cuda_runtime.h>
#include <cuda_fp16.h>
#include <cstdint>

#define BATCH 4
#define H 256
#define W 256
#define C0 32
#define C 64
#define HT 513
#define HO 511

// ---------------------------------------------------------------------------
// Scratch (static device memory; no cudaMalloc allowed)
// ---------------------------------------------------------------------------
__device__ float g_x0[BATCH * H * W * C0];
__device__ float g_mask0[BATCH * H * W];
__device__ float g_mask1[BATCH * H * W];
__device__ __align__(128) __half g_h1[BATCH * H * W * C];
__device__ __align__(128) __half g_h2[BATCH * H * W * C];
__device__ __align__(128) __half g_ht[BATCH * HT * HT * C];
__device__ float g_wT1[9 * 64 * 32];                 // conv1 (tf32)
__device__ __align__(128) __half g_wH2[9 * 64 * 64];
__device__ __align__(128) __half g_wH3[9 * 64 * 64];
__device__ __align__(128) __half g_wH4[9 * 64 * 64];
__device__ __align__(128) __half g_wH5[9 * 64 * 64];

// ---------------------------------------------------------------------------
// helpers
// ---------------------------------------------------------------------------
__device__ __forceinline__ uint32_t smem_u32(const void* p) {
    uint32_t a;
    asm("{ .reg .u64 t; cvta.to.shared.u64 t, %1; cvt.u32.u64 %0, t; }" : "=r"(a) : "l"(p));
    return a;
}
__device__ __forceinline__ float tf32r(float x) {
    float y;
    asm("cvt.rna.tf32.f32 %0, %1;" : "=f"(y) : "f"(x));
    return y;
}

#if defined(__CUDA_ARCH_FEAT_SM103_ALL) || defined(__CUDA_ARCH_FEAT_SM100_ALL) || !defined(__CUDA_ARCH__)
#define HAS_TCGEN05 1
#else
#define HAS_TCGEN05 0
#endif

#define MBARRIER_INIT(a, c) \
    asm volatile("mbarrier.init.shared.b64 [%0], %1;" :: "r"(a), "r"(c) : "memory")
#define MBARRIER_WAIT_PARITY(a, ph) do { \
    uint32_t _m = (a), _p = (ph), _d; \
    asm volatile("{\n\t.reg .pred p;\n\t" \
        "mbarrier.try_wait.parity.acquire.cta.shared::cta.b64 p, [%1], %2;\n\t" \
        "selp.b32 %0, 1, 0, p;\n\t}" : "=r"(_d) : "r"(_m), "r"(_p) : "memory"); \
    if (!_d) { \
        asm volatile("{\n\t.reg .pred P1;\n\t" \
            "WL_%=:\n\t" \
            "mbarrier.try_wait.parity.acquire.cta.shared::cta.b64 P1, [%0], %1, 0x989680;\n\t" \
            "@P1 bra.uni WD_%=;\n\t" \
            "bra.uni WL_%=;\n\t" \
            "WD_%=:\n\t}" :: "r"(_m), "r"(_p) : "memory"); \
    } } while (0)

#define TCGEN05_ALLOC(dst, n) \
    asm volatile("tcgen05.alloc.cta_group::1.sync.aligned.shared::cta.b32 [%0], %1;" \
                 :: "r"(dst), "r"(n) : "memory")
#define TCGEN05_RELINQ() \
    asm volatile("tcgen05.relinquish_alloc_permit.cta_group::1.sync.aligned;")
#define TCGEN05_DEALLOC(t, n) \
    asm volatile("tcgen05.dealloc.cta_group::1.sync.aligned.b32 %0, %1;" :: "r"(t), "r"(n))
#define TCGEN05_COMMIT(mb) \
    asm volatile("tcgen05.commit.cta_group::1.mbarrier::arrive::one.shared::cluster.b64 [%0];" \
                 :: "r"(mb) : "memory")
#define TCGEN05_FENCE_AFTER() asm volatile("tcgen05.fence::after_thread_sync;" ::: "memory")
#define TCGEN05_FENCE_BEFORE() asm volatile("tcgen05.fence::before_thread_sync;" ::: "memory")
#define TCGEN05_WAIT_LD() asm volatile("tcgen05.wait::ld.sync.aligned;" ::: "memory")
#define FENCE_PROXY_ASYNC() asm volatile("fence.proxy.async.shared::cta;" ::: "memory")

#define CP16(dst, src, nbytes) \
    asm volatile("cp.async.cg.shared.global [%0], [%1], 16, %2;" \
                 :: "r"(dst), "l"(src), "r"(nbytes) : "memory")
#define CP_COMMIT() asm volatile("cp.async.commit_group;" ::: "memory")
#define CP_WAIT0()  asm volatile("cp.async.wait_group 0;" ::: "memory")

#define TCGEN05_LD_X32(r, addr) \
    asm volatile("tcgen05.ld.sync.aligned.32x32b.x32.b32 " \
        "{%0,%1,%2,%3,%4,%5,%6,%7,%8,%9,%10,%11,%12,%13,%14,%15," \
        "%16,%17,%18,%19,%20,%21,%22,%23,%24,%25,%26,%27,%28,%29,%30,%31}, [%32];" \
        : "=r"((r)[0]), "=r"((r)[1]), "=r"((r)[2]), "=r"((r)[3]), \
          "=r"((r)[4]), "=r"((r)[5]), "=r"((r)[6]), "=r"((r)[7]), \
          "=r"((r)[8]), "=r"((r)[9]), "=r"((r)[10]), "=r"((r)[11]), \
          "=r"((r)[12]), "=r"((r)[13]), "=r"((r)[14]), "=r"((r)[15]), \
          "=r"((r)[16]), "=r"((r)[17]), "=r"((r)[18]), "=r"((r)[19]), \
          "=r"((r)[20]), "=r"((r)[21]), "=r"((r)[22]), "=r"((r)[23]), \
          "=r"((r)[24]), "=r"((r)[25]), "=r"((r)[26]), "=r"((r)[27]), \
          "=r"((r)[28]), "=r"((r)[29]), "=r"((r)[30]), "=r"((r)[31]) \
        : "r"(addr))

#define TF32_IDESC 0x8100910u
#define F16_IDESC  0x8100010u

#define TC_MMA_TF32(dt, ad, bd, en) \
    asm volatile("{\n\t.reg .pred p;\n\tsetp.ne.u32 p, %4, 0;\n\t" \
        "tcgen05.mma.cta_group::1.kind::tf32 [%0], %1, %2, %3, p;\n\t}" \
        :: "r"(dt), "l"(ad), "l"(bd), "r"(TF32_IDESC), "r"(en) : "memory")

#define TC_MMA_F16(dt, ad, bd, en) \
    asm volatile("{\n\t.reg .pred p;\n\tsetp.ne.u32 p, %4, 0;\n\t" \
        "tcgen05.mma.cta_group::1.kind::f16 [%0], %1, %2, %3, {%5,%5,%5,%5}, p;\n\t}" \
        :: "r"(dt), "l"(ad), "l"(bd), "r"(F16_IDESC), "r"(en), "r"(0u) : "memory")

#define DESC_BASE_SW128 \
    ((2ull << 61) | (1ull << 46) | (64ull << 32) | (1ull << 16))
#define MAKE_DESC(a) (DESC_BASE_SW128 | ((uint64_t)((a) >> 4) & 0x3FFF))

// ---------------------------------------------------------------------------
// Staging. fp16 CIN=64: 128B per pixel, single SW128 atom-column.
// M=256 tile staged by 256 threads: 8 A-chunks + 2 B-chunks per thread.
// ---------------------------------------------------------------------------
__device__ __forceinline__ void stage_A256h_cp(uint32_t a_s, int tid,
                                               const __half* __restrict__ rowp,
                                               int ixb, int iw_lim) {
#pragma unroll
    for (int it = 0; it < 8; it++) {
        int i = tid + it * 256;
        int c8 = i & 7, m = i >> 3;            // m in 0..255
        int ix = ixb + m;
        bool ok = (ix >= 0 && ix < iw_lim);
        const __half* src = rowp + (size_t)(ok ? ix : 0) * 64 + 8 * c8;
        uint32_t off = (uint32_t)m * 128u + (uint32_t)c8 * 16u;
        off ^= (off >> 3) & 0x70u;
        CP16(a_s + off, src, ok ? 16 : 0);
    }
}
__device__ __forceinline__ void stage_B64h_cp256(uint32_t b_s, int tid,
                                                 const __half* __restrict__ wk) {
#pragma unroll
    for (int it = 0; it < 2; it++) {
        int i = tid + it * 256;
        int c8 = i & 7, n = i >> 3;
        const __half* src = wk + (size_t)n * 64 + 8 * c8;
        uint32_t off = (uint32_t)n * 128u + (uint32_t)c8 * 16u;
        off ^= (off >> 3) & 0x70u;
        CP16(b_s + off, src, 16);
    }
}
// conv1 (CIN=32 fp32/tf32), M=128, 128 threads
__device__ __forceinline__ void stage_A32(char* aptr, int tid,
                                          const float* __restrict__ rowp,
                                          int ixb, int iw_lim) {
#pragma unroll
    for (int it = 0; it < 8; it++) {
        int i = tid + it * 128;
        int c4 = i & 7, m = i >> 3;
        int ix = ixb + m;
        float4 v = make_float4(0.f, 0.f, 0.f, 0.f);
        if (ix >= 0 && ix < iw_lim)
            v = *reinterpret_cast<const float4*>(rowp + (size_t)ix * 32 + 4 * c4);
        v.x = tf32r(v.x); v.y = tf32r(v.y); v.z = tf32r(v.z); v.w = tf32r(v.w);
        uint32_t off = (uint32_t)m * 128u + (uint32_t)c4 * 16u;
        off ^= (off >> 3) & 0x70u;
        *reinterpret_cast<float4*>(aptr + off) = v;
    }
}
__device__ __forceinline__ void stage_B32_cp(uint32_t b_s, int tid,
                                             const float* __restrict__ wk) {
#pragma unroll
    for (int it = 0; it < 4; it++) {
        int i = tid + it * 128;
        int c4 = i & 7, n = i >> 3;
        const float* src = wk + (size_t)n * 32 + 4 * c4;
        uint32_t off = (uint32_t)n * 128u + (uint32_t)c4 * 16u;
        off ^= (off >> 3) & 0x70u;
        CP16(b_s + off, src, 16);
    }
}

// ---------------------------------------------------------------------------
// Preprocess / scatter / mask kernels
// ---------------------------------------------------------------------------
__global__ void transposeW_all_kernel(const float* w2, const float* w3,
                                      const float* wt, const float* w5,
                                      const float* w1) {
    int which = blockIdx.y;
    int i = blockIdx.x * blockDim.x + threadIdx.x;
    if (which < 4) {
        if (i >= 9 * 64 * 64) return;
        const float* src[4] = {w2, w3, wt, w5};
        __half* dst[4] = {g_wH2, g_wH3, g_wH4, g_wH5};
        int co = i & 63, ci = (i >> 6) & 63, k = i >> 12;
        dst[which][(k * 64 + co) * 64 + ci] =
            __float2half_rn(src[which][(k * 64 + ci) * 64 + co]);
    } else {
        if (i >= 9 * 32 * 64) return;
        int co = i & 63, ci = (i >> 6) & 31, k = i >> 11;
        g_wT1[(k * 64 + co) * 32 + ci] = tf32r(w1[(k * 32 + ci) * 64 + co]);
    }
}

__global__ void zero_kernel() {
    int i = blockIdx.x * blockDim.x + threadIdx.x;
    if (i < BATCH * H * W * C0 / 4)
        reinterpret_cast<float4*>(g_x0)[i] = make_float4(0.f, 0.f, 0.f, 0.f);
    if (i < BATCH * H * W / 4)
        reinterpret_cast<float4*>(g_mask0)[i] = make_float4(0.f, 0.f, 0.f, 0.f);
}

__global__ void scatter_kernel(const float* __restrict__ feat,
                               const int* __restrict__ coors, int n) {
    int t = blockIdx.x * blockDim.x + threadIdx.x;
    int p = t >> 5, c = t & 31;
    if (p >= n) return;
    int b = coors[3 * p + 0], y = coors[3 * p + 1], x = coors[3 * p + 2];
    int pix = (b * H + y) * W + x;
    atomicAdd(&g_x0[pix * C0 + c], feat[p * C0 + c]);
    if (c == 0) g_mask0[pix] = 1.0f;
}

__global__ void mask1_kernel() {
    int i = blockIdx.x * blockDim.x + threadIdx.x;
    if (i >= BATCH * H * W) return;
    int x = i % W, y = (i / W) % H, b = i / (H * W);
    float m = 0.f;
#pragma unroll
    for (int dy = -1; dy <= 1; dy++)
#pragma unroll
        for (int dx = -1; dx <= 1; dx++) {
            int yy = y + dy, xx = x + dx;
            if (yy >= 0 && yy < H && xx >= 0 && xx < W)
                m = fmaxf(m, g_mask0[(b * H + yy) * W + xx]);
        }
    g_mask1[i] = (m > 0.f) ? 1.f : 0.f;
}

// ---------------------------------------------------------------------------
// Epilogues (one warp handles 32 pixels; D columns read from TMEM)
// ---------------------------------------------------------------------------
#if HAS_TCGEN05
__device__ __forceinline__ void tc_epi_f16(uint32_t tmem, const float* bias,
                                           float mval, __half* op, bool valid) {
    uint32_t dreg[64];
    TCGEN05_LD_X32(dreg, tmem);
    TCGEN05_LD_X32(dreg + 32, tmem + 32);
    TCGEN05_WAIT_LD();
    TCGEN05_FENCE_BEFORE();
    if (!valid) return;
#pragma unroll
    for (int c4 = 0; c4 < 16; c4++) {
        float4 bv = *reinterpret_cast<const float4*>(bias + 4 * c4);
        float vx = fmaxf((__uint_as_float(dreg[4 * c4 + 0]) + bv.x) * mval, 0.f);
        float vy = fmaxf((__uint_as_float(dreg[4 * c4 + 1]) + bv.y) * mval, 0.f);
        float vz = fmaxf((__uint_as_float(dreg[4 * c4 + 2]) + bv.z) * mval, 0.f);
        float vw = fmaxf((__uint_as_float(dreg[4 * c4 + 3]) + bv.w) * mval, 0.f);
        __half2 h0 = __floats2half2_rn(vx, vy);
        __half2 h1 = __floats2half2_rn(vz, vw);
        uint2 u;
        u.x = *reinterpret_cast<uint32_t*>(&h0);
        u.y = *reinterpret_cast<uint32_t*>(&h1);
        *reinterpret_cast<uint2*>(op + 4 * c4) = u;
    }
}
__device__ __forceinline__ void tc_epi_f32(uint32_t tmem, const float* bias,
                                           float mval, float* op, bool valid) {
    uint32_t dreg[64];
    TCGEN05_LD_X32(dreg, tmem);
    TCGEN05_LD_X32(dreg + 32, tmem + 32);
    TCGEN05_WAIT_LD();
    TCGEN05_FENCE_BEFORE();
    if (!valid) return;
#pragma unroll
    for (int c4 = 0; c4 < 16; c4++) {
        float4 bv = *reinterpret_cast<const float4*>(bias + 4 * c4);
        float4 v;
        v.x = fmaxf((__uint_as_float(dreg[4 * c4 + 0]) + bv.x) * mval, 0.f);
        v.y = fmaxf((__uint_as_float(dreg[4 * c4 + 1]) + bv.y) * mval, 0.f);
        v.z = fmaxf((__uint_as_float(dreg[4 * c4 + 2]) + bv.z) * mval, 0.f);
        v.w = fmaxf((__uint_as_float(dreg[4 * c4 + 3]) + bv.w) * mval, 0.f);
        *reinterpret_cast<float4*>(op + 4 * c4) = v;
    }
}
#endif

// ---------------------------------------------------------------------------
// conv1: CIN=32 tf32 (x0 fp32), M=128, 128 threads, output fp16 h1.
// ---------------------------------------------------------------------------
__global__ __launch_bounds__(128)
void conv1_tc_kernel(const float* __restrict__ in, const float* __restrict__ wT,
                     const float* __restrict__ bias, const float* __restrict__ mask,
                     __half* __restrict__ out) {
#if HAS_TCGEN05
    extern __shared__ char dsm[];
    __shared__ uint32_t s_tmem[1];
    __shared__ unsigned long long s_mbar;

    const int tid = threadIdx.x;
    const int wid = tid >> 5, lid = tid & 31;

    uint32_t dbase = smem_u32(dsm);
    uint32_t abase = (dbase + 1023u) & ~1023u;
    char* aptr = dsm + (abase - dbase);
    const uint32_t a_s = abase;
    const uint32_t b_s = abase + 16384;
    const uint32_t mbar = smem_u32(&s_mbar);

    if (wid == 0) {
        TCGEN05_ALLOC(smem_u32(&s_tmem[0]), 64);
        TCGEN05_RELINQ();
    }
    if (tid == 0) MBARRIER_INIT(mbar, 1);
    __syncthreads();
    const uint32_t tmem = s_tmem[0];

    const int x0 = blockIdx.x * 128;
    const int y = blockIdx.y;
    const int b = blockIdx.z;
    const float* inb = in + (size_t)b * H * W * 32;

    int phase = 0;
    bool first = true;

#pragma unroll 1
    for (int k = 0; k < 9; k++) {
        const int ky = k / 3, kx = k - ky * 3;
        const int row = y + ky - 1;
        if (row < 0 || row >= H) continue;

        stage_A32(aptr, tid, inb + (size_t)row * W * 32, x0 + kx - 1, W);
        stage_B32_cp(b_s, tid, wT + k * 2048);
        CP_COMMIT();
        CP_WAIT0();
        FENCE_PROXY_ASYNC();
        __syncthreads();

        if (tid == 0) {
            TCGEN05_FENCE_AFTER();
            uint64_t ad0 = MAKE_DESC(a_s);
            uint64_t bd0 = MAKE_DESC(b_s);
#pragma unroll
            for (int s = 0; s < 4; s++) {
                unsigned en = (first && s == 0) ? 0u : 1u;
                TC_MMA_TF32(tmem, ad0 + s * 2, bd0 + s * 2, en);
            }
            TCGEN05_COMMIT(mbar);
        }
        first = false;
        MBARRIER_WAIT_PARITY(mbar, phase);
        phase ^= 1;
    }

    TCGEN05_FENCE_AFTER();
    const int ox = x0 + wid * 32 + lid;
    float mval = mask[((size_t)b * H + y) * W + ox];
    __half* op = out + (((size_t)b * H + y) * W + ox) * 64;
    tc_epi_f16(tmem, bias, mval, op, true);

    __syncthreads();
    if (wid == 0) TCGEN05_DEALLOC(tmem, 64);
#else
    const int tid = threadIdx.x;
    const int ox = blockIdx.x * 128 + tid;
    const int y = blockIdx.y, b = blockIdx.z;
    const float* inb = in + (size_t)b * H * W * 32;
    float acc[64];
#pragma unroll
    for (int c = 0; c < 64; c++) acc[c] = 0.f;
    for (int k = 0; k < 9; k++) {
        const int ky = k / 3, kx = k - ky * 3;
        const int row = y + ky - 1, col = ox + kx - 1;
        if (row < 0 || row >= H || col < 0 || col >= W) continue;
        const float* ip = inb + ((size_t)row * W + col) * 32;
        const float* wk = wT + k * 2048;
        for (int ci = 0; ci < 32; ci++) {
            float iv = tf32r(ip[ci]);
#pragma unroll 16
            for (int co = 0; co < 64; co++)
                acc[co] = fmaf(iv, tf32r(wk[co * 32 + ci]), acc[co]);
        }
    }
    float mval = mask[((size_t)b * H + y) * W + ox];
    __half* op = out + (((size_t)b * H + y) * W + ox) * 64;
#pragma unroll
    for (int c = 0; c < 64; c++)
        op[c] = __float2half_rn(fmaxf((acc[c] + bias[c]) * mval, 0.f));
#endif
}

// ---------------------------------------------------------------------------
// conv (CIN=64 fp16), M=256, 256 threads, two 64-col TMEM accumulators.
// ---------------------------------------------------------------------------
template <bool MASK, bool OUT_HALF>
__global__ __launch_bounds__(256)
void conv64h_tc_kernel(const __half* __restrict__ in, const __half* __restrict__ wH,
                       const float* __restrict__ bias, const float* __restrict__ mask,
                       void* __restrict__ outv,
                       int IH, int IW, int OH, int OW, int pad) {
#if HAS_TCGEN05
    extern __shared__ char dsm[];
    __shared__ uint32_t s_tmem[1];
    __shared__ unsigned long long s_mbar;

    const int tid = threadIdx.x;
    const int wid = tid >> 5, lid = tid & 31;

    uint32_t dbase = smem_u32(dsm);
    uint32_t abase = (dbase + 1023u) & ~1023u;
    const uint32_t a_s = abase;
    const uint32_t b_s = abase + 32768;
    const uint32_t mbar = smem_u32(&s_mbar);

    if (wid == 0) {
        TCGEN05_ALLOC(smem_u32(&s_tmem[0]), 128);
        TCGEN05_RELINQ();
    }
    if (tid == 0) MBARRIER_INIT(mbar, 1);
    __syncthreads();
    const uint32_t tmem = s_tmem[0];

    const int x0 = blockIdx.x * 256;
    const int y = blockIdx.y;
    const int b = blockIdx.z;
    const __half* inb = in + (size_t)b * IH * IW * 64;

    int phase = 0;
    bool first = true;

#pragma unroll 1
    for (int k = 0; k < 9; k++) {
        const int ky = k / 3, kx = k - ky * 3;
        const int row = y + ky - pad;
        if (row < 0 || row >= IH) continue;

        stage_A256h_cp(a_s, tid, inb + (size_t)row * IW * 64, x0 + kx - pad, IW);
        stage_B64h_cp256(b_s, tid, wH + k * 4096);
        CP_COMMIT();
        CP_WAIT0();
        FENCE_PROXY_ASYNC();
        __syncthreads();

        if (tid == 0) {
            TCGEN05_FENCE_AFTER();
            uint64_t ad0 = MAKE_DESC(a_s);
            uint64_t bd0 = MAKE_DESC(b_s);
#pragma unroll
            for (int s = 0; s < 4; s++) {
                unsigned en = (first && s == 0) ? 0u : 1u;
                TC_MMA_F16(tmem, ad0 + s * 2, bd0 + s * 2, en);
                TC_MMA_F16(tmem + 64, ad0 + 1024 + s * 2, bd0 + s * 2, en);
            }
            TCGEN05_COMMIT(mbar);
        }
        first = false;
        MBARRIER_WAIT_PARITY(mbar, phase);
        phase ^= 1;
    }

    TCGEN05_FENCE_AFTER();

    const int half = wid >> 2;
    const int m = half * 128 + (wid & 3) * 32 + lid;
    const int ox = x0 + m;
    bool valid = (ox < OW);
    float mval = 1.0f;
    if (valid && MASK) mval = mask[((size_t)b * OH + y) * OW + ox];
    size_t pix = ((size_t)b * OH + y) * OW + ox;
    if (OUT_HALF)
        tc_epi_f16(tmem + half * 64, bias, mval, (__half*)outv + pix * 64, valid);
    else
        tc_epi_f32(tmem + half * 64, bias, mval, (float*)outv + pix * 64, valid);

    __syncthreads();
    if (wid == 0) TCGEN05_DEALLOC(tmem, 128);
#else
    const int tid = threadIdx.x;
    const int ox = blockIdx.x * 256 + tid;
    const int y = blockIdx.y, b = blockIdx.z;
    if (ox >= OW) return;
    const __half* inb = in + (size_t)b * IH * IW * 64;
    float acc[64];
#pragma unroll
    for (int c = 0; c < 64; c++) acc[c] = 0.f;
    for (int k = 0; k < 9; k++) {
        const int ky = k / 3, kx = k - ky * 3;
        const int row = y + ky - pad, col = ox + kx - pad;
        if (row < 0 || row >= IH || col < 0 || col >= IW) continue;
        const __half* ip = inb + ((size_t)row * IW + col) * 64;
        const __half* wk = wH + k * 4096;
        for (int ci = 0; ci < 64; ci++) {
            float iv = __half2float(ip[ci]);
#pragma unroll 16
            for (int co = 0; co < 64; co++)
                acc[co] = fmaf(iv, __half2float(wk[co * 64 + ci]), acc[co]);
        }
    }
    float mval = 1.0f;
    if (MASK) mval = mask[((size_t)b * OH + y) * OW + ox];
    size_t pix = ((size_t)b * OH + y) * OW + ox;
#pragma unroll
    for (int c = 0; c < 64; c++) {
        float v = fmaxf((acc[c] + bias[c]) * mval, 0.f);
        if (OUT_HALF) ((__half*)outv)[pix * 64 + c] = __float2half_rn(v);
        else ((float*)outv)[pix * 64 + c] = v;
    }
#endif
}

// ---------------------------------------------------------------------------
// conv_transpose fp16, parity-decomposed, M=256, 256 threads, inline mask4.
// ox(m) = cls + 2*m, m in 0..255 (covers ox <= 511; ox=512 via col512 kernel).
// ---------------------------------------------------------------------------
__global__ __launch_bounds__(256)
void convT_tc_kernel(const __half* __restrict__ in, const __half* __restrict__ wH,
                     const float* __restrict__ bias, const float* __restrict__ mask1,
                     __half* __restrict__ out) {
    const int cls = blockIdx.z & 1;
    const int b = blockIdx.z >> 1;
    const int oy = blockIdx.y;
#if HAS_TCGEN05
    extern __shared__ char dsm[];
    __shared__ uint32_t s_tmem[1];
    __shared__ unsigned long long s_mbar;

    const int tid = threadIdx.x;
    const int wid = tid >> 5, lid = tid & 31;

    uint32_t dbase = smem_u32(dsm);
    uint32_t abase = (dbase + 1023u) & ~1023u;
    const uint32_t a_s = abase;
    const uint32_t b_s = abase + 32768;
    const uint32_t mbar = smem_u32(&s_mbar);

    if (wid == 0) {
        TCGEN05_ALLOC(smem_u32(&s_tmem[0]), 128);
        TCGEN05_RELINQ();
    }
    if (tid == 0) MBARRIER_INIT(mbar, 1);
    __syncthreads();
    const uint32_t tmem = s_tmem[0];

    const __half* inb = in + (size_t)b * H * W * 64;
    const float* m1b = mask1 + (size_t)b * H * W;

    int phase = 0;
    bool first = true;

#pragma unroll 1
    for (int ky = 0; ky < 3; ky++) {
        if ((oy + ky) & 1) continue;
        const int iy = (oy + ky - 2) >> 1;
        if (iy < 0 || iy >= H) continue;
        const __half* rowp = inb + (size_t)iy * W * 64;
#pragma unroll 1
        for (int kx = 0; kx < 3; kx++) {
            if ((cls + kx) & 1) continue;
            const int ixb = (cls + kx - 2) >> 1;

            stage_A256h_cp(a_s, tid, rowp, ixb, W);
            stage_B64h_cp256(b_s, tid, wH + (ky * 3 + kx) * 4096);
            CP_COMMIT();
            CP_WAIT0();
            FENCE_PROXY_ASYNC();
            __syncthreads();

            if (tid == 0) {
                TCGEN05_FENCE_AFTER();
                uint64_t ad0 = MAKE_DESC(a_s);
                uint64_t bd0 = MAKE_DESC(b_s);
#pragma unroll
                for (int s = 0; s < 4; s++) {
                    unsigned en = (first && s == 0) ? 0u : 1u;
                    TC_MMA_F16(tmem, ad0 + s * 2, bd0 + s * 2, en);
                    TC_MMA_F16(tmem + 64, ad0 + 1024 + s * 2, bd0 + s * 2, en);
                }
                TCGEN05_COMMIT(mbar);
            }
            first = false;
            MBARRIER_WAIT_PARITY(mbar, phase);
            phase ^= 1;
        }
    }

    TCGEN05_FENCE_AFTER();

    const int half = wid >> 2;
    const int m = half * 128 + (wid & 3) * 32 + lid;
    const int ox = cls + 2 * m;
    bool valid = (ox < HT);
    float mval = 0.f;
    __half* op = nullptr;
    if (valid) {
#pragma unroll
        for (int ky = 0; ky < 3; ky++) {
            if ((oy + ky) & 1) continue;
            int iy = (oy + ky - 2) >> 1;
            if (iy < 0 || iy >= H) continue;
#pragma unroll
            for (int kx = 0; kx < 3; kx++) {
                if ((cls + kx) & 1) continue;
                int ix = (ox + kx - 2) >> 1;
                if (ix >= 0 && ix < W)
                    mval = fmaxf(mval, m1b[(size_t)iy * W + ix]);
            }
        }
        mval = (mval > 0.f) ? 1.f : 0.f;
        op = out + (((size_t)b * HT + oy) * HT + ox) * 64;
    }
    tc_epi_f16(tmem + half * 64, bias, mval, op, valid);

    __syncthreads();
    if (wid == 0) TCGEN05_DEALLOC(tmem, 128);
#else
    const int tid = threadIdx.x;
    const int ox = cls + 2 * tid;
    if (ox >= HT) return;
    const __half* inb = in + (size_t)b * H * W * 64;
    const float* m1b = mask1 + (size_t)b * H * W;
    float acc[64];
#pragma unroll
    for (int c = 0; c < 64; c++) acc[c] = 0.f;
    float mval = 0.f;
    for (int ky = 0; ky < 3; ky++) {
        if ((oy + ky) & 1) continue;
        int iy = (oy + ky - 2) >> 1;
        if (iy < 0 || iy >= H) continue;
        for (int kx = 0; kx < 3; kx++) {
            if ((cls + kx) & 1) continue;
            int ix = (ox + kx - 2) >> 1;
            if (ix < 0 || ix >= W) continue;
            mval = fmaxf(mval, m1b[(size_t)iy * W + ix]);
            const __half* ip = inb + ((size_t)iy * W + ix) * 64;
            const __half* wk = wH + (ky * 3 + kx) * 4096;
            for (int ci = 0; ci < 64; ci++) {
                float iv = __half2float(ip[ci]);
#pragma unroll 16
                for (int co = 0; co < 64; co++)
                    acc[co] = fmaf(iv, __half2float(wk[co * 64 + ci]), acc[co]);
            }
        }
    }
    mval = (mval > 0.f) ? 1.f : 0.f;
    __half* op = out + (((size_t)b * HT + oy) * HT + ox) * 64;
#pragma unroll
    for (int c = 0; c < 64; c++)
        op[c] = __float2half_rn(fmaxf((acc[c] + bias[c]) * mval, 0.f));
#endif
}

// ---------------------------------------------------------------------------
// ox=512 column of the conv_transpose (taps: ky even, kx=0, ix=255).
// ---------------------------------------------------------------------------
__global__ __launch_bounds__(64)
void convT_col512_kernel(const __half* __restrict__ in, const __half* __restrict__ wH,
                         const float* __restrict__ bias, const float* __restrict__ mask1,
                         __half* __restrict__ out) {
    const int oy = blockIdx.x, b = blockIdx.y, co = threadIdx.x;
    const __half* inb = in + (size_t)b * H * W * 64;
    const float* m1b = mask1 + (size_t)b * H * W;
    float acc = 0.f, mval = 0.f;
#pragma unroll
    for (int ky = 0; ky < 3; ky++) {
        if ((oy + ky) & 1) continue;
        int iy = (oy + ky - 2) >> 1;
        if (iy < 0 || iy >= H) continue;
        mval = fmaxf(mval, m1b[(size_t)iy * W + 255]);
        const __half* ip = inb + ((size_t)iy * W + 255) * 64;
        const __half* wk = wH + (ky * 3 + 0) * 4096 + co * 64;
#pragma unroll 16
        for (int ci = 0; ci < 64; ci++)
            acc = fmaf(__half2float(ip[ci]), __half2float(wk[ci]), acc);
    }
    mval = (mval > 0.f) ? 1.f : 0.f;
    out[(((size_t)b * HT + oy) * HT + 512) * 64 + co] =
        __float2half_rn(fmaxf((acc + bias[co]) * mval, 0.f));
}

// ---------------------------------------------------------------------------
// Launch
// ---------------------------------------------------------------------------
extern "C" void kernel_launch(void* const* d_in, const int* in_sizes, int n_in,
                              void* d_out, int out_size) {
    const float* features = (const float*)d_in[0];
    const int* coors      = (const int*)d_in[1];
    const float* w1 = (const float*)d_in[3];
    const float* b1 = (const float*)d_in[4];
    const float* w2 = (const float*)d_in[5];
    const float* b2 = (const float*)d_in[6];
    const float* w3 = (const float*)d_in[7];
    const float* b3 = (const float*)d_in[8];
    const float* wt = (const float*)d_in[9];
    const float* bt = (const float*)d_in[10];
    const float* w5 = (const float*)d_in[11];
    const float* b5 = (const float*)d_in[12];
    float* out = (float*)d_out;

    const int N = in_sizes[0] / C0;

    float *x0, *m1, *wT1;
    __half *h1, *h2, *ht, *wH2, *wH3, *wH4, *wH5;
    cudaGetSymbolAddress((void**)&x0, g_x0);
    cudaGetSymbolAddress((void**)&m1, g_mask1);
    cudaGetSymbolAddress((void**)&h1, g_h1);
    cudaGetSymbolAddress((void**)&h2, g_h2);
    cudaGetSymbolAddress((void**)&ht, g_ht);
    cudaGetSymbolAddress((void**)&wT1, g_wT1);
    cudaGetSymbolAddress((void**)&wH2, g_wH2);
    cudaGetSymbolAddress((void**)&wH3, g_wH3);
    cudaGetSymbolAddress((void**)&wH4, g_wH4);
    cudaGetSymbolAddress((void**)&wH5, g_wH5);

    const int SM1 = 1024 + 16384 + 8192;   // conv1 (M=128): 25600
    const int SM2 = 1024 + 32768 + 8192;   // M=256 fp16: 41984 -> 4 CTAs/SM (TMEM-capped)
    cudaFuncSetAttribute((const void*)conv64h_tc_kernel<true, true>,
                         cudaFuncAttributeMaxDynamicSharedMemorySize, SM2);
    cudaFuncSetAttribute((const void*)conv64h_tc_kernel<false, false>,
                         cudaFuncAttributeMaxDynamicSharedMemorySize, SM2);
    cudaFuncSetAttribute((const void*)conv1_tc_kernel,
                         cudaFuncAttributeMaxDynamicSharedMemorySize, SM1);
    cudaFuncSetAttribute((const void*)convT_tc_kernel,
                         cudaFuncAttributeMaxDynamicSharedMemorySize, SM2);

    {
        dim3 g((9 * 64 * 64 + 255) / 256, 5);
        transposeW_all_kernel<<<g, 256>>>(w2, w3, wt, w5, w1);
    }

    {
        int n4 = BATCH * H * W * C0 / 4;
        zero_kernel<<<(n4 + 255) / 256, 256>>>();
    }
    scatter_kernel<<<(N * 32 + 255) / 256, 256>>>(features, coors, N);
    mask1_kernel<<<(BATCH * H * W + 255) / 256, 256>>>();

    {
        dim3 g1(W / 128, H, BATCH);
        conv1_tc_kernel<<<g1, 128, SM1>>>(x0, wT1, b1, m1, h1);
        dim3 g2(W / 256, H, BATCH);
        conv64h_tc_kernel<true, true><<<g2, 256, SM2>>>(
            h1, wH2, b2, m1, h2, H, W, H, W, 1);
        conv64h_tc_kernel<true, true><<<g2, 256, SM2>>>(
            h2, wH3, b3, m1, h1, H, W, H, W, 1);
    }
    {
        dim3 grid(1, HT, BATCH * 2);
        convT_tc_kernel<<<grid, 256, SM2>>>(h1, wH4, bt, m1, ht);
        dim3 gcol(HT, BATCH);
        convT_col512_kernel<<<gcol, 64>>>(h1, wH4, bt, m1, ht);
    }
    {
        dim3 grid((HO + 255) / 256, HO, BATCH);
        conv64h_tc_kernel<false, false><<<grid, 256, SM2>>>(
            ht, wH5, b5, nullptr, out, HT, HT, HO, HO, 0);
    }
}

// round 16
// speedup vs baseline: 1.1474x; 1.1474x over previous
#include <cuda_runtime.h>
#include <cuda_fp16.h>
#include <cstdint>

#define BATCH 4
#define H 256
#define W 256
#define C0 32
#define C 64
#define HT 513
#define HO 511

// ---------------------------------------------------------------------------
// Scratch (static device memory; no cudaMalloc allowed)
// ---------------------------------------------------------------------------
__device__ float g_x0[BATCH * H * W * C0];
__device__ float g_mask0[BATCH * H * W];
__device__ float g_mask1[BATCH * H * W];
__device__ __align__(128) __half g_h1[BATCH * H * W * C];
__device__ __align__(128) __half g_h2[BATCH * H * W * C];
__device__ __align__(128) __half g_ht[BATCH * HT * HT * C];
__device__ float g_wT1[9 * 64 * 32];                 // conv1 (tf32)
__device__ __align__(128) __half g_wH2[9 * 64 * 64];
__device__ __align__(128) __half g_wH3[9 * 64 * 64];
__device__ __align__(128) __half g_wH4[9 * 64 * 64];
__device__ __align__(128) __half g_wH5[9 * 64 * 64];

// ---------------------------------------------------------------------------
// helpers
// ---------------------------------------------------------------------------
__device__ __forceinline__ uint32_t smem_u32(const void* p) {
    uint32_t a;
    asm("{ .reg .u64 t; cvta.to.shared.u64 t, %1; cvt.u32.u64 %0, t; }" : "=r"(a) : "l"(p));
    return a;
}
__device__ __forceinline__ float tf32r(float x) {
    float y;
    asm("cvt.rna.tf32.f32 %0, %1;" : "=f"(y) : "f"(x));
    return y;
}

#if defined(__CUDA_ARCH_FEAT_SM103_ALL) || defined(__CUDA_ARCH_FEAT_SM100_ALL) || !defined(__CUDA_ARCH__)
#define HAS_TCGEN05 1
#else
#define HAS_TCGEN05 0
#endif

#define MBARRIER_INIT(a, c) \
    asm volatile("mbarrier.init.shared.b64 [%0], %1;" :: "r"(a), "r"(c) : "memory")
#define MBARRIER_WAIT_PARITY(a, ph) do { \
    uint32_t _m = (a), _p = (ph), _d; \
    asm volatile("{\n\t.reg .pred p;\n\t" \
        "mbarrier.try_wait.parity.acquire.cta.shared::cta.b64 p, [%1], %2;\n\t" \
        "selp.b32 %0, 1, 0, p;\n\t}" : "=r"(_d) : "r"(_m), "r"(_p) : "memory"); \
    if (!_d) { \
        asm volatile("{\n\t.reg .pred P1;\n\t" \
            "WL_%=:\n\t" \
            "mbarrier.try_wait.parity.acquire.cta.shared::cta.b64 P1, [%0], %1, 0x989680;\n\t" \
            "@P1 bra.uni WD_%=;\n\t" \
            "bra.uni WL_%=;\n\t" \
            "WD_%=:\n\t}" :: "r"(_m), "r"(_p) : "memory"); \
    } } while (0)

#define TCGEN05_ALLOC(dst, n) \
    asm volatile("tcgen05.alloc.cta_group::1.sync.aligned.shared::cta.b32 [%0], %1;" \
                 :: "r"(dst), "r"(n) : "memory")
#define TCGEN05_RELINQ() \
    asm volatile("tcgen05.relinquish_alloc_permit.cta_group::1.sync.aligned;")
#define TCGEN05_DEALLOC(t, n) \
    asm volatile("tcgen05.dealloc.cta_group::1.sync.aligned.b32 %0, %1;" :: "r"(t), "r"(n))
#define TCGEN05_COMMIT(mb) \
    asm volatile("tcgen05.commit.cta_group::1.mbarrier::arrive::one.shared::cluster.b64 [%0];" \
                 :: "r"(mb) : "memory")
#define TCGEN05_FENCE_AFTER() asm volatile("tcgen05.fence::after_thread_sync;" ::: "memory")
#define TCGEN05_FENCE_BEFORE() asm volatile("tcgen05.fence::before_thread_sync;" ::: "memory")
#define TCGEN05_WAIT_LD() asm volatile("tcgen05.wait::ld.sync.aligned;" ::: "memory")
#define FENCE_PROXY_ASYNC() asm volatile("fence.proxy.async.shared::cta;" ::: "memory")

#define CP16(dst, src, nbytes) \
    asm volatile("cp.async.cg.shared.global [%0], [%1], 16, %2;" \
                 :: "r"(dst), "l"(src), "r"(nbytes) : "memory")
#define CP_COMMIT() asm volatile("cp.async.commit_group;" ::: "memory")
#define CP_WAIT0()  asm volatile("cp.async.wait_group 0;" ::: "memory")

#define TCGEN05_LD_X32(r, addr) \
    asm volatile("tcgen05.ld.sync.aligned.32x32b.x32.b32 " \
        "{%0,%1,%2,%3,%4,%5,%6,%7,%8,%9,%10,%11,%12,%13,%14,%15," \
        "%16,%17,%18,%19,%20,%21,%22,%23,%24,%25,%26,%27,%28,%29,%30,%31}, [%32];" \
        : "=r"((r)[0]), "=r"((r)[1]), "=r"((r)[2]), "=r"((r)[3]), \
          "=r"((r)[4]), "=r"((r)[5]), "=r"((r)[6]), "=r"((r)[7]), \
          "=r"((r)[8]), "=r"((r)[9]), "=r"((r)[10]), "=r"((r)[11]), \
          "=r"((r)[12]), "=r"((r)[13]), "=r"((r)[14]), "=r"((r)[15]), \
          "=r"((r)[16]), "=r"((r)[17]), "=r"((r)[18]), "=r"((r)[19]), \
          "=r"((r)[20]), "=r"((r)[21]), "=r"((r)[22]), "=r"((r)[23]), \
          "=r"((r)[24]), "=r"((r)[25]), "=r"((r)[26]), "=r"((r)[27]), \
          "=r"((r)[28]), "=r"((r)[29]), "=r"((r)[30]), "=r"((r)[31]) \
        : "r"(addr))

#define TF32_IDESC 0x8100910u
#define F16_IDESC  0x8100010u

#define TC_MMA_TF32(dt, ad, bd, en) \
    asm volatile("{\n\t.reg .pred p;\n\tsetp.ne.u32 p, %4, 0;\n\t" \
        "tcgen05.mma.cta_group::1.kind::tf32 [%0], %1, %2, %3, p;\n\t}" \
        :: "r"(dt), "l"(ad), "l"(bd), "r"(TF32_IDESC), "r"(en) : "memory")

#define TC_MMA_F16(dt, ad, bd, en) \
    asm volatile("{\n\t.reg .pred p;\n\tsetp.ne.u32 p, %4, 0;\n\t" \
        "tcgen05.mma.cta_group::1.kind::f16 [%0], %1, %2, %3, {%5,%5,%5,%5}, p;\n\t}" \
        :: "r"(dt), "l"(ad), "l"(bd), "r"(F16_IDESC), "r"(en), "r"(0u) : "memory")

#define DESC_BASE_SW128 \
    ((2ull << 61) | (1ull << 46) | (64ull << 32) | (1ull << 16))
#define MAKE_DESC(a) (DESC_BASE_SW128 | ((uint64_t)((a) >> 4) & 0x3FFF))

// ---------------------------------------------------------------------------
// Staging (128 threads, M=128). fp16 CIN=64: 128B/pixel, single atom-column.
// ---------------------------------------------------------------------------
__device__ __forceinline__ void stage_A64h_cp(uint32_t a_s, int tid,
                                              const __half* __restrict__ rowp,
                                              int ixb, int iw_lim) {
#pragma unroll
    for (int it = 0; it < 8; it++) {
        int i = tid + it * 128;
        int c8 = i & 7, m = i >> 3;
        int ix = ixb + m;
        bool ok = (ix >= 0 && ix < iw_lim);
        const __half* src = rowp + (size_t)(ok ? ix : 0) * 64 + 8 * c8;
        uint32_t off = (uint32_t)m * 128u + (uint32_t)c8 * 16u;
        off ^= (off >> 3) & 0x70u;
        CP16(a_s + off, src, ok ? 16 : 0);
    }
}
__device__ __forceinline__ void stage_B64h_cp(uint32_t b_s, int tid,
                                              const __half* __restrict__ wk) {
#pragma unroll
    for (int it = 0; it < 4; it++) {
        int i = tid + it * 128;
        int c8 = i & 7, n = i >> 3;
        const __half* src = wk + (size_t)n * 64 + 8 * c8;
        uint32_t off = (uint32_t)n * 128u + (uint32_t)c8 * 16u;
        off ^= (off >> 3) & 0x70u;
        CP16(b_s + off, src, 16);
    }
}
// conv1 (CIN=32 fp32/tf32) paths
__device__ __forceinline__ void stage_A32(char* aptr, int tid,
                                          const float* __restrict__ rowp,
                                          int ixb, int iw_lim) {
#pragma unroll
    for (int it = 0; it < 8; it++) {
        int i = tid + it * 128;
        int c4 = i & 7, m = i >> 3;
        int ix = ixb + m;
        float4 v = make_float4(0.f, 0.f, 0.f, 0.f);
        if (ix >= 0 && ix < iw_lim)
            v = *reinterpret_cast<const float4*>(rowp + (size_t)ix * 32 + 4 * c4);
        v.x = tf32r(v.x); v.y = tf32r(v.y); v.z = tf32r(v.z); v.w = tf32r(v.w);
        uint32_t off = (uint32_t)m * 128u + (uint32_t)c4 * 16u;
        off ^= (off >> 3) & 0x70u;
        *reinterpret_cast<float4*>(aptr + off) = v;
    }
}
__device__ __forceinline__ void stage_B32_cp(uint32_t b_s, int tid,
                                             const float* __restrict__ wk) {
#pragma unroll
    for (int it = 0; it < 4; it++) {
        int i = tid + it * 128;
        int c4 = i & 7, n = i >> 3;
        const float* src = wk + (size_t)n * 32 + 4 * c4;
        uint32_t off = (uint32_t)n * 128u + (uint32_t)c4 * 16u;
        off ^= (off >> 3) & 0x70u;
        CP16(b_s + off, src, 16);
    }
}

// ---------------------------------------------------------------------------
// Preprocess / scatter / mask kernels
// ---------------------------------------------------------------------------
__global__ void transposeW_all_kernel(const float* w2, const float* w3,
                                      const float* wt, const float* w5,
                                      const float* w1) {
    int which = blockIdx.y;
    int i = blockIdx.x * blockDim.x + threadIdx.x;
    if (which < 4) {
        if (i >= 9 * 64 * 64) return;
        const float* src[4] = {w2, w3, wt, w5};
        __half* dst[4] = {g_wH2, g_wH3, g_wH4, g_wH5};
        int co = i & 63, ci = (i >> 6) & 63, k = i >> 12;
        dst[which][(k * 64 + co) * 64 + ci] =
            __float2half_rn(src[which][(k * 64 + ci) * 64 + co]);
    } else {
        if (i >= 9 * 32 * 64) return;
        int co = i & 63, ci = (i >> 6) & 31, k = i >> 11;
        g_wT1[(k * 64 + co) * 32 + ci] = tf32r(w1[(k * 32 + ci) * 64 + co]);
    }
}

__global__ void zero_kernel() {
    int i = blockIdx.x * blockDim.x + threadIdx.x;
    if (i < BATCH * H * W * C0 / 4)
        reinterpret_cast<float4*>(g_x0)[i] = make_float4(0.f, 0.f, 0.f, 0.f);
    if (i < BATCH * H * W / 4)
        reinterpret_cast<float4*>(g_mask0)[i] = make_float4(0.f, 0.f, 0.f, 0.f);
}

__global__ void scatter_kernel(const float* __restrict__ feat,
                               const int* __restrict__ coors, int n) {
    int t = blockIdx.x * blockDim.x + threadIdx.x;
    int p = t >> 5, c = t & 31;
    if (p >= n) return;
    int b = coors[3 * p + 0], y = coors[3 * p + 1], x = coors[3 * p + 2];
    int pix = (b * H + y) * W + x;
    atomicAdd(&g_x0[pix * C0 + c], feat[p * C0 + c]);
    if (c == 0) g_mask0[pix] = 1.0f;
}

__global__ void mask1_kernel() {
    int i = blockIdx.x * blockDim.x + threadIdx.x;
    if (i >= BATCH * H * W) return;
    int x = i % W, y = (i / W) % H, b = i / (H * W);
    float m = 0.f;
#pragma unroll
    for (int dy = -1; dy <= 1; dy++)
#pragma unroll
        for (int dx = -1; dx <= 1; dx++) {
            int yy = y + dy, xx = x + dx;
            if (yy >= 0 && yy < H && xx >= 0 && xx < W)
                m = fmaxf(m, g_mask0[(b * H + yy) * W + xx]);
        }
    g_mask1[i] = (m > 0.f) ? 1.f : 0.f;
}

// ---------------------------------------------------------------------------
// Epilogues
// ---------------------------------------------------------------------------
#if HAS_TCGEN05
__device__ __forceinline__ void tc_epi_f16(uint32_t tmem, const float* bias,
                                           float mval, __half* op, bool valid) {
    uint32_t dreg[64];
    TCGEN05_LD_X32(dreg, tmem);
    TCGEN05_LD_X32(dreg + 32, tmem + 32);
    TCGEN05_WAIT_LD();
    TCGEN05_FENCE_BEFORE();
    if (!valid) return;
#pragma unroll
    for (int c4 = 0; c4 < 16; c4++) {
        float4 bv = *reinterpret_cast<const float4*>(bias + 4 * c4);
        float vx = fmaxf((__uint_as_float(dreg[4 * c4 + 0]) + bv.x) * mval, 0.f);
        float vy = fmaxf((__uint_as_float(dreg[4 * c4 + 1]) + bv.y) * mval, 0.f);
        float vz = fmaxf((__uint_as_float(dreg[4 * c4 + 2]) + bv.z) * mval, 0.f);
        float vw = fmaxf((__uint_as_float(dreg[4 * c4 + 3]) + bv.w) * mval, 0.f);
        __half2 h0 = __floats2half2_rn(vx, vy);
        __half2 h1 = __floats2half2_rn(vz, vw);
        uint2 u;
        u.x = *reinterpret_cast<uint32_t*>(&h0);
        u.y = *reinterpret_cast<uint32_t*>(&h1);
        *reinterpret_cast<uint2*>(op + 4 * c4) = u;
    }
}
__device__ __forceinline__ void tc_epi_f32(uint32_t tmem, const float* bias,
                                           float mval, float* op, bool valid) {
    uint32_t dreg[64];
    TCGEN05_LD_X32(dreg, tmem);
    TCGEN05_LD_X32(dreg + 32, tmem + 32);
    TCGEN05_WAIT_LD();
    TCGEN05_FENCE_BEFORE();
    if (!valid) return;
#pragma unroll
    for (int c4 = 0; c4 < 16; c4++) {
        float4 bv = *reinterpret_cast<const float4*>(bias + 4 * c4);
        float4 v;
        v.x = fmaxf((__uint_as_float(dreg[4 * c4 + 0]) + bv.x) * mval, 0.f);
        v.y = fmaxf((__uint_as_float(dreg[4 * c4 + 1]) + bv.y) * mval, 0.f);
        v.z = fmaxf((__uint_as_float(dreg[4 * c4 + 2]) + bv.z) * mval, 0.f);
        v.w = fmaxf((__uint_as_float(dreg[4 * c4 + 3]) + bv.w) * mval, 0.f);
        *reinterpret_cast<float4*>(op + 4 * c4) = v;
    }
}
#endif

// ---------------------------------------------------------------------------
// conv1: CIN=32 tf32 (x0 fp32), output fp16 h1.
// ---------------------------------------------------------------------------
__global__ __launch_bounds__(128)
void conv1_tc_kernel(const float* __restrict__ in, const float* __restrict__ wT,
                     const float* __restrict__ bias, const float* __restrict__ mask,
                     __half* __restrict__ out) {
#if HAS_TCGEN05
    extern __shared__ char dsm[];
    __shared__ uint32_t s_tmem[1];
    __shared__ unsigned long long s_mbar;

    const int tid = threadIdx.x;
    const int wid = tid >> 5, lid = tid & 31;

    uint32_t dbase = smem_u32(dsm);
    uint32_t abase = (dbase + 1023u) & ~1023u;
    char* aptr = dsm + (abase - dbase);
    const uint32_t a_s = abase;
    const uint32_t b_s = abase + 16384;
    const uint32_t mbar = smem_u32(&s_mbar);

    if (wid == 0) {
        TCGEN05_ALLOC(smem_u32(&s_tmem[0]), 64);
        TCGEN05_RELINQ();
    }
    if (tid == 0) MBARRIER_INIT(mbar, 1);
    __syncthreads();
    const uint32_t tmem = s_tmem[0];

    const int x0 = blockIdx.x * 128;
    const int y = blockIdx.y;
    const int b = blockIdx.z;
    const float* inb = in + (size_t)b * H * W * 32;

    int phase = 0;
    bool first = true;

#pragma unroll 1
    for (int k = 0; k < 9; k++) {
        const int ky = k / 3, kx = k - ky * 3;
        const int row = y + ky - 1;
        if (row < 0 || row >= H) continue;

        stage_A32(aptr, tid, inb + (size_t)row * W * 32, x0 + kx - 1, W);
        stage_B32_cp(b_s, tid, wT + k * 2048);
        CP_COMMIT();
        CP_WAIT0();
        FENCE_PROXY_ASYNC();
        __syncthreads();

        if (tid == 0) {
            TCGEN05_FENCE_AFTER();
            uint64_t ad0 = MAKE_DESC(a_s);
            uint64_t bd0 = MAKE_DESC(b_s);
#pragma unroll
            for (int s = 0; s < 4; s++) {
                unsigned en = (first && s == 0) ? 0u : 1u;
                TC_MMA_TF32(tmem, ad0 + s * 2, bd0 + s * 2, en);
            }
            TCGEN05_COMMIT(mbar);
        }
        first = false;
        MBARRIER_WAIT_PARITY(mbar, phase);
        phase ^= 1;
    }

    TCGEN05_FENCE_AFTER();
    const int ox = x0 + wid * 32 + lid;
    float mval = mask[((size_t)b * H + y) * W + ox];
    __half* op = out + (((size_t)b * H + y) * W + ox) * 64;
    tc_epi_f16(tmem, bias, mval, op, true);

    __syncthreads();
    if (wid == 0) TCGEN05_DEALLOC(tmem, 64);
#else
    const int tid = threadIdx.x;
    const int ox = blockIdx.x * 128 + tid;
    const int y = blockIdx.y, b = blockIdx.z;
    const float* inb = in + (size_t)b * H * W * 32;
    float acc[64];
#pragma unroll
    for (int c = 0; c < 64; c++) acc[c] = 0.f;
    for (int k = 0; k < 9; k++) {
        const int ky = k / 3, kx = k - ky * 3;
        const int row = y + ky - 1, col = ox + kx - 1;
        if (row < 0 || row >= H || col < 0 || col >= W) continue;
        const float* ip = inb + ((size_t)row * W + col) * 32;
        const float* wk = wT + k * 2048;
        for (int ci = 0; ci < 32; ci++) {
            float iv = tf32r(ip[ci]);
#pragma unroll 16
            for (int co = 0; co < 64; co++)
                acc[co] = fmaf(iv, tf32r(wk[co * 32 + ci]), acc[co]);
        }
    }
    float mval = mask[((size_t)b * H + y) * W + ox];
    __half* op = out + (((size_t)b * H + y) * W + ox) * 64;
#pragma unroll
    for (int c = 0; c < 64; c++)
        op[c] = __float2half_rn(fmaxf((acc[c] + bias[c]) * mval, 0.f));
#endif
}

// ---------------------------------------------------------------------------
// conv (CIN=64 fp16), per-tap cp.async staging, fp32 accum.
// ---------------------------------------------------------------------------
template <bool MASK, bool OUT_HALF>
__global__ __launch_bounds__(128)
void conv64h_tc_kernel(const __half* __restrict__ in, const __half* __restrict__ wH,
                       const float* __restrict__ bias, const float* __restrict__ mask,
                       void* __restrict__ outv,
                       int IH, int IW, int OH, int OW, int pad) {
#if HAS_TCGEN05
    extern __shared__ char dsm[];
    __shared__ uint32_t s_tmem[1];
    __shared__ unsigned long long s_mbar;

    const int tid = threadIdx.x;
    const int wid = tid >> 5, lid = tid & 31;

    uint32_t dbase = smem_u32(dsm);
    uint32_t abase = (dbase + 1023u) & ~1023u;
    const uint32_t a_s = abase;
    const uint32_t b_s = abase + 16384;
    const uint32_t mbar = smem_u32(&s_mbar);

    if (wid == 0) {
        TCGEN05_ALLOC(smem_u32(&s_tmem[0]), 64);
        TCGEN05_RELINQ();
    }
    if (tid == 0) MBARRIER_INIT(mbar, 1);
    __syncthreads();
    const uint32_t tmem = s_tmem[0];

    const int x0 = blockIdx.x * 128;
    const int y = blockIdx.y;
    const int b = blockIdx.z;
    const __half* inb = in + (size_t)b * IH * IW * 64;

    int phase = 0;
    bool first = true;

#pragma unroll 1
    for (int k = 0; k < 9; k++) {
        const int ky = k / 3, kx = k - ky * 3;
        const int row = y + ky - pad;
        if (row < 0 || row >= IH) continue;

        stage_A64h_cp(a_s, tid, inb + (size_t)row * IW * 64, x0 + kx - pad, IW);
        stage_B64h_cp(b_s, tid, wH + k * 4096);
        CP_COMMIT();
        CP_WAIT0();
        FENCE_PROXY_ASYNC();
        __syncthreads();

        if (tid == 0) {
            TCGEN05_FENCE_AFTER();
            uint64_t ad0 = MAKE_DESC(a_s);
            uint64_t bd0 = MAKE_DESC(b_s);
#pragma unroll
            for (int s = 0; s < 4; s++) {
                unsigned en = (first && s == 0) ? 0u : 1u;
                TC_MMA_F16(tmem, ad0 + s * 2, bd0 + s * 2, en);
            }
            TCGEN05_COMMIT(mbar);
        }
        first = false;
        MBARRIER_WAIT_PARITY(mbar, phase);
        phase ^= 1;
    }

    TCGEN05_FENCE_AFTER();

    const int ox = x0 + wid * 32 + lid;
    bool valid = (ox < OW);
    float mval = 1.0f;
    if (valid && MASK) mval = mask[((size_t)b * OH + y) * OW + ox];
    size_t pix = ((size_t)b * OH + y) * OW + ox;
    if (OUT_HALF)
        tc_epi_f16(tmem, bias, mval, (__half*)outv + pix * 64, valid);
    else
        tc_epi_f32(tmem, bias, mval, (float*)outv + pix * 64, valid);

    __syncthreads();
    if (wid == 0) TCGEN05_DEALLOC(tmem, 64);
#else
    const int tid = threadIdx.x;
    const int ox = blockIdx.x * 128 + tid;
    const int y = blockIdx.y, b = blockIdx.z;
    if (ox >= OW) return;
    const __half* inb = in + (size_t)b * IH * IW * 64;
    float acc[64];
#pragma unroll
    for (int c = 0; c < 64; c++) acc[c] = 0.f;
    for (int k = 0; k < 9; k++) {
        const int ky = k / 3, kx = k - ky * 3;
        const int row = y + ky - pad, col = ox + kx - pad;
        if (row < 0 || row >= IH || col < 0 || col >= IW) continue;
        const __half* ip = inb + ((size_t)row * IW + col) * 64;
        const __half* wk = wH + k * 4096;
        for (int ci = 0; ci < 64; ci++) {
            float iv = __half2float(ip[ci]);
#pragma unroll 16
            for (int co = 0; co < 64; co++)
                acc[co] = fmaf(iv, __half2float(wk[co * 64 + ci]), acc[co]);
        }
    }
    float mval = 1.0f;
    if (MASK) mval = mask[((size_t)b * OH + y) * OW + ox];
    size_t pix = ((size_t)b * OH + y) * OW + ox;
#pragma unroll
    for (int c = 0; c < 64; c++) {
        float v = fmaxf((acc[c] + bias[c]) * mval, 0.f);
        if (OUT_HALF) ((__half*)outv)[pix * 64 + c] = __float2half_rn(v);
        else ((float*)outv)[pix * 64 + c] = v;
    }
#endif
}

// ---------------------------------------------------------------------------
// conv_transpose fp16, parity-decomposed, inline mask4, fp16 output.
// ---------------------------------------------------------------------------
__global__ __launch_bounds__(128)
void convT_tc_kernel(const __half* __restrict__ in, const __half* __restrict__ wH,
                     const float* __restrict__ bias, const float* __restrict__ mask1,
                     __half* __restrict__ out) {
    const int cls = blockIdx.z & 1;
    const int b = blockIdx.z >> 1;
    const int oy = blockIdx.y;
    const int xbase = blockIdx.x * 256 + cls;
    if (xbase >= HT) return;
#if HAS_TCGEN05
    extern __shared__ char dsm[];
    __shared__ uint32_t s_tmem[1];
    __shared__ unsigned long long s_mbar;

    const int tid = threadIdx.x;
    const int wid = tid >> 5, lid = tid & 31;

    uint32_t dbase = smem_u32(dsm);
    uint32_t abase = (dbase + 1023u) & ~1023u;
    const uint32_t a_s = abase;
    const uint32_t b_s = abase + 16384;
    const uint32_t mbar = smem_u32(&s_mbar);

    if (wid == 0) {
        TCGEN05_ALLOC(smem_u32(&s_tmem[0]), 64);
        TCGEN05_RELINQ();
    }
    if (tid == 0) MBARRIER_INIT(mbar, 1);
    __syncthreads();
    const uint32_t tmem = s_tmem[0];

    const __half* inb = in + (size_t)b * H * W * 64;
    const float* m1b = mask1 + (size_t)b * H * W;

    int phase = 0;
    bool first = true;

#pragma unroll 1
    for (int ky = 0; ky < 3; ky++) {
        if ((oy + ky) & 1) continue;
        const int iy = (oy + ky - 2) >> 1;
        if (iy < 0 || iy >= H) continue;
        const __half* rowp = inb + (size_t)iy * W * 64;
#pragma unroll 1
        for (int kx = 0; kx < 3; kx++) {
            if ((cls + kx) & 1) continue;
            const int ixb = (xbase + kx - 2) >> 1;

            stage_A64h_cp(a_s, tid, rowp, ixb, W);
            stage_B64h_cp(b_s, tid, wH + (ky * 3 + kx) * 4096);
            CP_COMMIT();
            CP_WAIT0();
            FENCE_PROXY_ASYNC();
            __syncthreads();

            if (tid == 0) {
                TCGEN05_FENCE_AFTER();
                uint64_t ad0 = MAKE_DESC(a_s);
                uint64_t bd0 = MAKE_DESC(b_s);
#pragma unroll
                for (int s = 0; s < 4; s++) {
                    unsigned en = (first && s == 0) ? 0u : 1u;
                    TC_MMA_F16(tmem, ad0 + s * 2, bd0 + s * 2, en);
                }
                TCGEN05_COMMIT(mbar);
            }
            first = false;
            MBARRIER_WAIT_PARITY(mbar, phase);
            phase ^= 1;
        }
    }

    TCGEN05_FENCE_AFTER();

    const int m = wid * 32 + lid;
    const int ox = xbase + 2 * m;
    bool valid = (ox < HT);
    float mval = 0.f;
    __half* op = nullptr;
    if (valid) {
#pragma unroll
        for (int ky = 0; ky < 3; ky++) {
            if ((oy + ky) & 1) continue;
            int iy = (oy + ky - 2) >> 1;
            if (iy < 0 || iy >= H) continue;
#pragma unroll
            for (int kx = 0; kx < 3; kx++) {
                if ((cls + kx) & 1) continue;
                int ix = (ox + kx - 2) >> 1;
                if (ix >= 0 && ix < W)
                    mval = fmaxf(mval, m1b[(size_t)iy * W + ix]);
            }
        }
        mval = (mval > 0.f) ? 1.f : 0.f;
        op = out + (((size_t)b * HT + oy) * HT + ox) * 64;
    }
    tc_epi_f16(tmem, bias, mval, op, valid);

    __syncthreads();
    if (wid == 0) TCGEN05_DEALLOC(tmem, 64);
#else
    const int tid = threadIdx.x;
    const int ox = xbase + 2 * tid;
    if (ox >= HT) return;
    const __half* inb = in + (size_t)b * H * W * 64;
    const float* m1b = mask1 + (size_t)b * H * W;
    float acc[64];
#pragma unroll
    for (int c = 0; c < 64; c++) acc[c] = 0.f;
    float mval = 0.f;
    for (int ky = 0; ky < 3; ky++) {
        if ((oy + ky) & 1) continue;
        int iy = (oy + ky - 2) >> 1;
        if (iy < 0 || iy >= H) continue;
        for (int kx = 0; kx < 3; kx++) {
            if ((cls + kx) & 1) continue;
            int ix = (ox + kx - 2) >> 1;
            if (ix < 0 || ix >= W) continue;
            mval = fmaxf(mval, m1b[(size_t)iy * W + ix]);
            const __half* ip = inb + ((size_t)iy * W + ix) * 64;
            const __half* wk = wH + (ky * 3 + kx) * 4096;
            for (int ci = 0; ci < 64; ci++) {
                float iv = __half2float(ip[ci]);
#pragma unroll 16
                for (int co = 0; co < 64; co++)
                    acc[co] = fmaf(iv, __half2float(wk[co * 64 + ci]), acc[co]);
            }
        }
    }
    mval = (mval > 0.f) ? 1.f : 0.f;
    __half* op = out + (((size_t)b * HT + oy) * HT + ox) * 64;
#pragma unroll
    for (int c = 0; c < 64; c++)
        op[c] = __float2half_rn(fmaxf((acc[c] + bias[c]) * mval, 0.f));
#endif
}

// ---------------------------------------------------------------------------
// Launch
// ---------------------------------------------------------------------------
extern "C" void kernel_launch(void* const* d_in, const int* in_sizes, int n_in,
                              void* d_out, int out_size) {
    const float* features = (const float*)d_in[0];
    const int* coors      = (const int*)d_in[1];
    const float* w1 = (const float*)d_in[3];
    const float* b1 = (const float*)d_in[4];
    const float* w2 = (const float*)d_in[5];
    const float* b2 = (const float*)d_in[6];
    const float* w3 = (const float*)d_in[7];
    const float* b3 = (const float*)d_in[8];
    const float* wt = (const float*)d_in[9];
    const float* bt = (const float*)d_in[10];
    const float* w5 = (const float*)d_in[11];
    const float* b5 = (const float*)d_in[12];
    float* out = (float*)d_out;

    const int N = in_sizes[0] / C0;

    float *x0, *m1, *wT1;
    __half *h1, *h2, *ht, *wH2, *wH3, *wH4, *wH5;
    cudaGetSymbolAddress((void**)&x0, g_x0);
    cudaGetSymbolAddress((void**)&m1, g_mask1);
    cudaGetSymbolAddress((void**)&h1, g_h1);
    cudaGetSymbolAddress((void**)&h2, g_h2);
    cudaGetSymbolAddress((void**)&ht, g_ht);
    cudaGetSymbolAddress((void**)&wT1, g_wT1);
    cudaGetSymbolAddress((void**)&wH2, g_wH2);
    cudaGetSymbolAddress((void**)&wH3, g_wH3);
    cudaGetSymbolAddress((void**)&wH4, g_wH4);
    cudaGetSymbolAddress((void**)&wH5, g_wH5);

    const int SMH = 1024 + 16384 + 8192;   // 25600 -> 8 CTAs/SM
    cudaFuncSetAttribute((const void*)conv64h_tc_kernel<true, true>,
                         cudaFuncAttributeMaxDynamicSharedMemorySize, SMH);
    cudaFuncSetAttribute((const void*)conv64h_tc_kernel<false, false>,
                         cudaFuncAttributeMaxDynamicSharedMemorySize, SMH);
    cudaFuncSetAttribute((const void*)conv1_tc_kernel,
                         cudaFuncAttributeMaxDynamicSharedMemorySize, SMH);
    cudaFuncSetAttribute((const void*)convT_tc_kernel,
                         cudaFuncAttributeMaxDynamicSharedMemorySize, SMH);

    {
        dim3 g((9 * 64 * 64 + 255) / 256, 5);
        transposeW_all_kernel<<<g, 256>>>(w2, w3, wt, w5, w1);
    }

    {
        int n4 = BATCH * H * W * C0 / 4;
        zero_kernel<<<(n4 + 255) / 256, 256>>>();
    }
    scatter_kernel<<<(N * 32 + 255) / 256, 256>>>(features, coors, N);
    mask1_kernel<<<(BATCH * H * W + 255) / 256, 256>>>();

    {
        dim3 grid(W / 128, H, BATCH);
        conv1_tc_kernel<<<grid, 128, SMH>>>(x0, wT1, b1, m1, h1);
        conv64h_tc_kernel<true, true><<<grid, 128, SMH>>>(
            h1, wH2, b2, m1, h2, H, W, H, W, 1);
        conv64h_tc_kernel<true, true><<<grid, 128, SMH>>>(
            h2, wH3, b3, m1, h1, H, W, H, W, 1);
    }
    {
        dim3 grid(3, HT, BATCH * 2);
        convT_tc_kernel<<<grid, 128, SMH>>>(h1, wH4, bt, m1, ht);
    }
    {
        dim3 grid((HO + 127) / 128, HO, BATCH);
        conv64h_tc_kernel<false, false><<<grid, 128, SMH>>>(
            ht, wH5, b5, nullptr, out, HT, HT, HO, HO, 0);
    }
}

// round 17
// speedup vs baseline: 1.1713x; 1.0209x over previous
#include <cuda_runtime.h>
#include <cuda_fp16.h>
#include <cstdint>

#define BATCH 4
#define H 256
#define W 256
#define C0 32
#define C 64
#define HT 513
#define HO 511

// ---------------------------------------------------------------------------
// Scratch (static device memory; no cudaMalloc allowed)
// ---------------------------------------------------------------------------
__device__ __align__(128) __half g_x0h[BATCH * H * W * C0];   // fp16 scatter target
__device__ float g_mask0[BATCH * H * W];
__device__ float g_mask1[BATCH * H * W];
__device__ __align__(128) __half g_h1[BATCH * H * W * C];
__device__ __align__(128) __half g_h2[BATCH * H * W * C];
__device__ __align__(128) __half g_ht[BATCH * HT * HT * C];
__device__ float g_wT1[9 * 64 * 32];                 // conv1 (tf32)
__device__ __align__(128) __half g_wH2[9 * 64 * 64];
__device__ __align__(128) __half g_wH3[9 * 64 * 64];
__device__ __align__(128) __half g_wH4[9 * 64 * 64];
__device__ __align__(128) __half g_wH5[9 * 64 * 64];

// ---------------------------------------------------------------------------
// helpers
// ---------------------------------------------------------------------------
__device__ __forceinline__ uint32_t smem_u32(const void* p) {
    uint32_t a;
    asm("{ .reg .u64 t; cvta.to.shared.u64 t, %1; cvt.u32.u64 %0, t; }" : "=r"(a) : "l"(p));
    return a;
}
__device__ __forceinline__ float tf32r(float x) {
    float y;
    asm("cvt.rna.tf32.f32 %0, %1;" : "=f"(y) : "f"(x));
    return y;
}

#if defined(__CUDA_ARCH_FEAT_SM103_ALL) || defined(__CUDA_ARCH_FEAT_SM100_ALL) || !defined(__CUDA_ARCH__)
#define HAS_TCGEN05 1
#else
#define HAS_TCGEN05 0
#endif

#define MBARRIER_INIT(a, c) \
    asm volatile("mbarrier.init.shared.b64 [%0], %1;" :: "r"(a), "r"(c) : "memory")
#define MBARRIER_WAIT_PARITY(a, ph) do { \
    uint32_t _m = (a), _p = (ph), _d; \
    asm volatile("{\n\t.reg .pred p;\n\t" \
        "mbarrier.try_wait.parity.acquire.cta.shared::cta.b64 p, [%1], %2;\n\t" \
        "selp.b32 %0, 1, 0, p;\n\t}" : "=r"(_d) : "r"(_m), "r"(_p) : "memory"); \
    if (!_d) { \
        asm volatile("{\n\t.reg .pred P1;\n\t" \
            "WL_%=:\n\t" \
            "mbarrier.try_wait.parity.acquire.cta.shared::cta.b64 P1, [%0], %1, 0x989680;\n\t" \
            "@P1 bra.uni WD_%=;\n\t" \
            "bra.uni WL_%=;\n\t" \
            "WD_%=:\n\t}" :: "r"(_m), "r"(_p) : "memory"); \
    } } while (0)

#define TCGEN05_ALLOC(dst, n) \
    asm volatile("tcgen05.alloc.cta_group::1.sync.aligned.shared::cta.b32 [%0], %1;" \
                 :: "r"(dst), "r"(n) : "memory")
#define TCGEN05_RELINQ() \
    asm volatile("tcgen05.relinquish_alloc_permit.cta_group::1.sync.aligned;")
#define TCGEN05_DEALLOC(t, n) \
    asm volatile("tcgen05.dealloc.cta_group::1.sync.aligned.b32 %0, %1;" :: "r"(t), "r"(n))
#define TCGEN05_COMMIT(mb) \
    asm volatile("tcgen05.commit.cta_group::1.mbarrier::arrive::one.shared::cluster.b64 [%0];" \
                 :: "r"(mb) : "memory")
#define TCGEN05_FENCE_AFTER() asm volatile("tcgen05.fence::after_thread_sync;" ::: "memory")
#define TCGEN05_FENCE_BEFORE() asm volatile("tcgen05.fence::before_thread_sync;" ::: "memory")
#define TCGEN05_WAIT_LD() asm volatile("tcgen05.wait::ld.sync.aligned;" ::: "memory")
#define FENCE_PROXY_ASYNC() asm volatile("fence.proxy.async.shared::cta;" ::: "memory")

#define CP16(dst, src, nbytes) \
    asm volatile("cp.async.cg.shared.global [%0], [%1], 16, %2;" \
                 :: "r"(dst), "l"(src), "r"(nbytes) : "memory")
#define CP_COMMIT() asm volatile("cp.async.commit_group;" ::: "memory")
#define CP_WAIT0()  asm volatile("cp.async.wait_group 0;" ::: "memory")

#define TCGEN05_LD_X32(r, addr) \
    asm volatile("tcgen05.ld.sync.aligned.32x32b.x32.b32 " \
        "{%0,%1,%2,%3,%4,%5,%6,%7,%8,%9,%10,%11,%12,%13,%14,%15," \
        "%16,%17,%18,%19,%20,%21,%22,%23,%24,%25,%26,%27,%28,%29,%30,%31}, [%32];" \
        : "=r"((r)[0]), "=r"((r)[1]), "=r"((r)[2]), "=r"((r)[3]), \
          "=r"((r)[4]), "=r"((r)[5]), "=r"((r)[6]), "=r"((r)[7]), \
          "=r"((r)[8]), "=r"((r)[9]), "=r"((r)[10]), "=r"((r)[11]), \
          "=r"((r)[12]), "=r"((r)[13]), "=r"((r)[14]), "=r"((r)[15]), \
          "=r"((r)[16]), "=r"((r)[17]), "=r"((r)[18]), "=r"((r)[19]), \
          "=r"((r)[20]), "=r"((r)[21]), "=r"((r)[22]), "=r"((r)[23]), \
          "=r"((r)[24]), "=r"((r)[25]), "=r"((r)[26]), "=r"((r)[27]), \
          "=r"((r)[28]), "=r"((r)[29]), "=r"((r)[30]), "=r"((r)[31]) \
        : "r"(addr))

#define TF32_IDESC 0x8100910u
#define F16_IDESC  0x8100010u

#define TC_MMA_TF32(dt, ad, bd, en) \
    asm volatile("{\n\t.reg .pred p;\n\tsetp.ne.u32 p, %4, 0;\n\t" \
        "tcgen05.mma.cta_group::1.kind::tf32 [%0], %1, %2, %3, p;\n\t}" \
        :: "r"(dt), "l"(ad), "l"(bd), "r"(TF32_IDESC), "r"(en) : "memory")

#define TC_MMA_F16(dt, ad, bd, en) \
    asm volatile("{\n\t.reg .pred p;\n\tsetp.ne.u32 p, %4, 0;\n\t" \
        "tcgen05.mma.cta_group::1.kind::f16 [%0], %1, %2, %3, {%5,%5,%5,%5}, p;\n\t}" \
        :: "r"(dt), "l"(ad), "l"(bd), "r"(F16_IDESC), "r"(en), "r"(0u) : "memory")

#define DESC_BASE_SW128 \
    ((2ull << 61) | (1ull << 46) | (64ull << 32) | (1ull << 16))
#define MAKE_DESC(a) (DESC_BASE_SW128 | ((uint64_t)((a) >> 4) & 0x3FFF))

// ---------------------------------------------------------------------------
// Staging (128 threads, M=128). fp16 CIN=64: 128B/pixel, single atom-column.
// ---------------------------------------------------------------------------
__device__ __forceinline__ void stage_A64h_cp(uint32_t a_s, int tid,
                                              const __half* __restrict__ rowp,
                                              int ixb, int iw_lim) {
#pragma unroll
    for (int it = 0; it < 8; it++) {
        int i = tid + it * 128;
        int c8 = i & 7, m = i >> 3;
        int ix = ixb + m;
        bool ok = (ix >= 0 && ix < iw_lim);
        const __half* src = rowp + (size_t)(ok ? ix : 0) * 64 + 8 * c8;
        uint32_t off = (uint32_t)m * 128u + (uint32_t)c8 * 16u;
        off ^= (off >> 3) & 0x70u;
        CP16(a_s + off, src, ok ? 16 : 0);
    }
}
__device__ __forceinline__ void stage_B64h_cp(uint32_t b_s, int tid,
                                              const __half* __restrict__ wk) {
#pragma unroll
    for (int it = 0; it < 4; it++) {
        int i = tid + it * 128;
        int c8 = i & 7, n = i >> 3;
        const __half* src = wk + (size_t)n * 64 + 8 * c8;
        uint32_t off = (uint32_t)n * 128u + (uint32_t)c8 * 16u;
        off ^= (off >> 3) & 0x70u;
        CP16(b_s + off, src, 16);
    }
}
// conv1: A from fp16 x0 -> fp32 smem (fp16 values are exactly representable
// in tf32, so no explicit rounding needed).
__device__ __forceinline__ void stage_A32h(char* aptr, int tid,
                                           const __half* __restrict__ rowp,
                                           int ixb, int iw_lim) {
#pragma unroll
    for (int it = 0; it < 8; it++) {
        int i = tid + it * 128;
        int c4 = i & 7, m = i >> 3;
        int ix = ixb + m;
        float4 v = make_float4(0.f, 0.f, 0.f, 0.f);
        if (ix >= 0 && ix < iw_lim) {
            uint2 raw = *reinterpret_cast<const uint2*>(rowp + (size_t)ix * 32 + 4 * c4);
            __half2 h0 = *reinterpret_cast<__half2*>(&raw.x);
            __half2 h1 = *reinterpret_cast<__half2*>(&raw.y);
            float2 f0 = __half22float2(h0);
            float2 f1 = __half22float2(h1);
            v = make_float4(f0.x, f0.y, f1.x, f1.y);
        }
        uint32_t off = (uint32_t)m * 128u + (uint32_t)c4 * 16u;
        off ^= (off >> 3) & 0x70u;
        *reinterpret_cast<float4*>(aptr + off) = v;
    }
}
__device__ __forceinline__ void stage_B32_cp(uint32_t b_s, int tid,
                                             const float* __restrict__ wk) {
#pragma unroll
    for (int it = 0; it < 4; it++) {
        int i = tid + it * 128;
        int c4 = i & 7, n = i >> 3;
        const float* src = wk + (size_t)n * 32 + 4 * c4;
        uint32_t off = (uint32_t)n * 128u + (uint32_t)c4 * 16u;
        off ^= (off >> 3) & 0x70u;
        CP16(b_s + off, src, 16);
    }
}

// ---------------------------------------------------------------------------
// Preprocess / scatter / mask kernels
// ---------------------------------------------------------------------------
__global__ void transposeW_all_kernel(const float* w2, const float* w3,
                                      const float* wt, const float* w5,
                                      const float* w1) {
    int which = blockIdx.y;
    int i = blockIdx.x * blockDim.x + threadIdx.x;
    if (which < 4) {
        if (i >= 9 * 64 * 64) return;
        const float* src[4] = {w2, w3, wt, w5};
        __half* dst[4] = {g_wH2, g_wH3, g_wH4, g_wH5};
        int co = i & 63, ci = (i >> 6) & 63, k = i >> 12;
        dst[which][(k * 64 + co) * 64 + ci] =
            __float2half_rn(src[which][(k * 64 + ci) * 64 + co]);
    } else {
        if (i >= 9 * 32 * 64) return;
        int co = i & 63, ci = (i >> 6) & 31, k = i >> 11;
        g_wT1[(k * 64 + co) * 32 + ci] = tf32r(w1[(k * 32 + ci) * 64 + co]);
    }
}

__global__ void zero_kernel() {
    int i = blockIdx.x * blockDim.x + threadIdx.x;
    // x0h: BATCH*H*W*32 halves = 8 halves per uint4
    if (i < BATCH * H * W * C0 / 8)
        reinterpret_cast<uint4*>(g_x0h)[i] = make_uint4(0, 0, 0, 0);
    if (i < BATCH * H * W / 4)
        reinterpret_cast<float4*>(g_mask0)[i] = make_float4(0.f, 0.f, 0.f, 0.f);
}

// 16 threads per point; each handles a channel pair via half2 atomics.
__global__ void scatter_kernel(const float* __restrict__ feat,
                               const int* __restrict__ coors, int n) {
    int t = blockIdx.x * blockDim.x + threadIdx.x;
    int p = t >> 4, c = t & 15;
    if (p >= n) return;
    int b = coors[3 * p + 0], y = coors[3 * p + 1], x = coors[3 * p + 2];
    int pix = (b * H + y) * W + x;
    float2 f = *reinterpret_cast<const float2*>(feat + (size_t)p * C0 + 2 * c);
    __half2 h = __floats2half2_rn(f.x, f.y);
    atomicAdd(reinterpret_cast<__half2*>(g_x0h + (size_t)pix * C0 + 2 * c), h);
    if (c == 0) g_mask0[pix] = 1.0f;
}

__global__ void mask1_kernel() {
    int i = blockIdx.x * blockDim.x + threadIdx.x;
    if (i >= BATCH * H * W) return;
    int x = i % W, y = (i / W) % H, b = i / (H * W);
    float m = 0.f;
#pragma unroll
    for (int dy = -1; dy <= 1; dy++)
#pragma unroll
        for (int dx = -1; dx <= 1; dx++) {
            int yy = y + dy, xx = x + dx;
            if (yy >= 0 && yy < H && xx >= 0 && xx < W)
                m = fmaxf(m, g_mask0[(b * H + yy) * W + xx]);
        }
    g_mask1[i] = (m > 0.f) ? 1.f : 0.f;
}

// ---------------------------------------------------------------------------
// Epilogues
// ---------------------------------------------------------------------------
#if HAS_TCGEN05
__device__ __forceinline__ void tc_epi_f16(uint32_t tmem, const float* bias,
                                           float mval, __half* op, bool valid) {
    uint32_t dreg[64];
    TCGEN05_LD_X32(dreg, tmem);
    TCGEN05_LD_X32(dreg + 32, tmem + 32);
    TCGEN05_WAIT_LD();
    TCGEN05_FENCE_BEFORE();
    if (!valid) return;
#pragma unroll
    for (int c4 = 0; c4 < 16; c4++) {
        float4 bv = *reinterpret_cast<const float4*>(bias + 4 * c4);
        float vx = fmaxf((__uint_as_float(dreg[4 * c4 + 0]) + bv.x) * mval, 0.f);
        float vy = fmaxf((__uint_as_float(dreg[4 * c4 + 1]) + bv.y) * mval, 0.f);
        float vz = fmaxf((__uint_as_float(dreg[4 * c4 + 2]) + bv.z) * mval, 0.f);
        float vw = fmaxf((__uint_as_float(dreg[4 * c4 + 3]) + bv.w) * mval, 0.f);
        __half2 h0 = __floats2half2_rn(vx, vy);
        __half2 h1 = __floats2half2_rn(vz, vw);
        uint2 u;
        u.x = *reinterpret_cast<uint32_t*>(&h0);
        u.y = *reinterpret_cast<uint32_t*>(&h1);
        *reinterpret_cast<uint2*>(op + 4 * c4) = u;
    }
}
__device__ __forceinline__ void tc_epi_f32(uint32_t tmem, const float* bias,
                                           float mval, float* op, bool valid) {
    uint32_t dreg[64];
    TCGEN05_LD_X32(dreg, tmem);
    TCGEN05_LD_X32(dreg + 32, tmem + 32);
    TCGEN05_WAIT_LD();
    TCGEN05_FENCE_BEFORE();
    if (!valid) return;
#pragma unroll
    for (int c4 = 0; c4 < 16; c4++) {
        float4 bv = *reinterpret_cast<const float4*>(bias + 4 * c4);
        float4 v;
        v.x = fmaxf((__uint_as_float(dreg[4 * c4 + 0]) + bv.x) * mval, 0.f);
        v.y = fmaxf((__uint_as_float(dreg[4 * c4 + 1]) + bv.y) * mval, 0.f);
        v.z = fmaxf((__uint_as_float(dreg[4 * c4 + 2]) + bv.z) * mval, 0.f);
        v.w = fmaxf((__uint_as_float(dreg[4 * c4 + 3]) + bv.w) * mval, 0.f);
        *reinterpret_cast<float4*>(op + 4 * c4) = v;
    }
}
#endif

// ---------------------------------------------------------------------------
// conv1: CIN=32 tf32 (x0 fp16 source), output fp16 h1.
// ---------------------------------------------------------------------------
__global__ __launch_bounds__(128)
void conv1_tc_kernel(const __half* __restrict__ in, const float* __restrict__ wT,
                     const float* __restrict__ bias, const float* __restrict__ mask,
                     __half* __restrict__ out) {
#if HAS_TCGEN05
    extern __shared__ char dsm[];
    __shared__ uint32_t s_tmem[1];
    __shared__ unsigned long long s_mbar;

    const int tid = threadIdx.x;
    const int wid = tid >> 5, lid = tid & 31;

    uint32_t dbase = smem_u32(dsm);
    uint32_t abase = (dbase + 1023u) & ~1023u;
    char* aptr = dsm + (abase - dbase);
    const uint32_t a_s = abase;
    const uint32_t b_s = abase + 16384;
    const uint32_t mbar = smem_u32(&s_mbar);

    if (wid == 0) {
        TCGEN05_ALLOC(smem_u32(&s_tmem[0]), 64);
        TCGEN05_RELINQ();
    }
    if (tid == 0) MBARRIER_INIT(mbar, 1);
    __syncthreads();
    const uint32_t tmem = s_tmem[0];

    const int x0 = blockIdx.x * 128;
    const int y = blockIdx.y;
    const int b = blockIdx.z;
    const __half* inb = in + (size_t)b * H * W * 32;

    int phase = 0;
    bool first = true;

#pragma unroll 1
    for (int k = 0; k < 9; k++) {
        const int ky = k / 3, kx = k - ky * 3;
        const int row = y + ky - 1;
        if (row < 0 || row >= H) continue;

        stage_A32h(aptr, tid, inb + (size_t)row * W * 32, x0 + kx - 1, W);
        stage_B32_cp(b_s, tid, wT + k * 2048);
        CP_COMMIT();
        CP_WAIT0();
        FENCE_PROXY_ASYNC();
        __syncthreads();

        if (tid == 0) {
            TCGEN05_FENCE_AFTER();
            uint64_t ad0 = MAKE_DESC(a_s);
            uint64_t bd0 = MAKE_DESC(b_s);
#pragma unroll
            for (int s = 0; s < 4; s++) {
                unsigned en = (first && s == 0) ? 0u : 1u;
                TC_MMA_TF32(tmem, ad0 + s * 2, bd0 + s * 2, en);
            }
            TCGEN05_COMMIT(mbar);
        }
        first = false;
        MBARRIER_WAIT_PARITY(mbar, phase);
        phase ^= 1;
    }

    TCGEN05_FENCE_AFTER();
    const int ox = x0 + wid * 32 + lid;
    float mval = mask[((size_t)b * H + y) * W + ox];
    __half* op = out + (((size_t)b * H + y) * W + ox) * 64;
    tc_epi_f16(tmem, bias, mval, op, true);

    __syncthreads();
    if (wid == 0) TCGEN05_DEALLOC(tmem, 64);
#else
    const int tid = threadIdx.x;
    const int ox = blockIdx.x * 128 + tid;
    const int y = blockIdx.y, b = blockIdx.z;
    const __half* inb = in + (size_t)b * H * W * 32;
    float acc[64];
#pragma unroll
    for (int c = 0; c < 64; c++) acc[c] = 0.f;
    for (int k = 0; k < 9; k++) {
        const int ky = k / 3, kx = k - ky * 3;
        const int row = y + ky - 1, col = ox + kx - 1;
        if (row < 0 || row >= H || col < 0 || col >= W) continue;
        const __half* ip = inb + ((size_t)row * W + col) * 32;
        const float* wk = wT + k * 2048;
        for (int ci = 0; ci < 32; ci++) {
            float iv = __half2float(ip[ci]);
#pragma unroll 16
            for (int co = 0; co < 64; co++)
                acc[co] = fmaf(iv, tf32r(wk[co * 32 + ci]), acc[co]);
        }
    }
    float mval = mask[((size_t)b * H + y) * W + ox];
    __half* op = out + (((size_t)b * H + y) * W + ox) * 64;
#pragma unroll
    for (int c = 0; c < 64; c++)
        op[c] = __float2half_rn(fmaxf((acc[c] + bias[c]) * mval, 0.f));
#endif
}

// ---------------------------------------------------------------------------
// conv (CIN=64 fp16), per-tap cp.async staging, fp32 accum.
// ---------------------------------------------------------------------------
template <bool MASK, bool OUT_HALF>
__global__ __launch_bounds__(128)
void conv64h_tc_kernel(const __half* __restrict__ in, const __half* __restrict__ wH,
                       const float* __restrict__ bias, const float* __restrict__ mask,
                       void* __restrict__ outv,
                       int IH, int IW, int OH, int OW, int pad) {
#if HAS_TCGEN05
    extern __shared__ char dsm[];
    __shared__ uint32_t s_tmem[1];
    __shared__ unsigned long long s_mbar;

    const int tid = threadIdx.x;
    const int wid = tid >> 5, lid = tid & 31;

    uint32_t dbase = smem_u32(dsm);
    uint32_t abase = (dbase + 1023u) & ~1023u;
    const uint32_t a_s = abase;
    const uint32_t b_s = abase + 16384;
    const uint32_t mbar = smem_u32(&s_mbar);

    if (wid == 0) {
        TCGEN05_ALLOC(smem_u32(&s_tmem[0]), 64);
        TCGEN05_RELINQ();
    }
    if (tid == 0) MBARRIER_INIT(mbar, 1);
    __syncthreads();
    const uint32_t tmem = s_tmem[0];

    const int x0 = blockIdx.x * 128;
    const int y = blockIdx.y;
    const int b = blockIdx.z;
    const __half* inb = in + (size_t)b * IH * IW * 64;

    int phase = 0;
    bool first = true;

#pragma unroll 1
    for (int k = 0; k < 9; k++) {
        const int ky = k / 3, kx = k - ky * 3;
        const int row = y + ky - pad;
        if (row < 0 || row >= IH) continue;

        stage_A64h_cp(a_s, tid, inb + (size_t)row * IW * 64, x0 + kx - pad, IW);
        stage_B64h_cp(b_s, tid, wH + k * 4096);
        CP_COMMIT();
        CP_WAIT0();
        FENCE_PROXY_ASYNC();
        __syncthreads();

        if (tid == 0) {
            TCGEN05_FENCE_AFTER();
            uint64_t ad0 = MAKE_DESC(a_s);
            uint64_t bd0 = MAKE_DESC(b_s);
#pragma unroll
            for (int s = 0; s < 4; s++) {
                unsigned en = (first && s == 0) ? 0u : 1u;
                TC_MMA_F16(tmem, ad0 + s * 2, bd0 + s * 2, en);
            }
            TCGEN05_COMMIT(mbar);
        }
        first = false;
        MBARRIER_WAIT_PARITY(mbar, phase);
        phase ^= 1;
    }

    TCGEN05_FENCE_AFTER();

    const int ox = x0 + wid * 32 + lid;
    bool valid = (ox < OW);
    float mval = 1.0f;
    if (valid && MASK) mval = mask[((size_t)b * OH + y) * OW + ox];
    size_t pix = ((size_t)b * OH + y) * OW + ox;
    if (OUT_HALF)
        tc_epi_f16(tmem, bias, mval, (__half*)outv + pix * 64, valid);
    else
        tc_epi_f32(tmem, bias, mval, (float*)outv + pix * 64, valid);

    __syncthreads();
    if (wid == 0) TCGEN05_DEALLOC(tmem, 64);
#else
    const int tid = threadIdx.x;
    const int ox = blockIdx.x * 128 + tid;
    const int y = blockIdx.y, b = blockIdx.z;
    if (ox >= OW) return;
    const __half* inb = in + (size_t)b * IH * IW * 64;
    float acc[64];
#pragma unroll
    for (int c = 0; c < 64; c++) acc[c] = 0.f;
    for (int k = 0; k < 9; k++) {
        const int ky = k / 3, kx = k - ky * 3;
        const int row = y + ky - pad, col = ox + kx - pad;
        if (row < 0 || row >= IH || col < 0 || col >= IW) continue;
        const __half* ip = inb + ((size_t)row * IW + col) * 64;
        const __half* wk = wH + k * 4096;
        for (int ci = 0; ci < 64; ci++) {
            float iv = __half2float(ip[ci]);
#pragma unroll 16
            for (int co = 0; co < 64; co++)
                acc[co] = fmaf(iv, __half2float(wk[co * 64 + ci]), acc[co]);
        }
    }
    float mval = 1.0f;
    if (MASK) mval = mask[((size_t)b * OH + y) * OW + ox];
    size_t pix = ((size_t)b * OH + y) * OW + ox;
#pragma unroll
    for (int c = 0; c < 64; c++) {
        float v = fmaxf((acc[c] + bias[c]) * mval, 0.f);
        if (OUT_HALF) ((__half*)outv)[pix * 64 + c] = __float2half_rn(v);
        else ((float*)outv)[pix * 64 + c] = v;
    }
#endif
}

// ---------------------------------------------------------------------------
// conv_transpose fp16, parity-decomposed, inline mask4, fp16 output.
// ---------------------------------------------------------------------------
__global__ __launch_bounds__(128)
void convT_tc_kernel(const __half* __restrict__ in, const __half* __restrict__ wH,
                     const float* __restrict__ bias, const float* __restrict__ mask1,
                     __half* __restrict__ out) {
    const int cls = blockIdx.z & 1;
    const int b = blockIdx.z >> 1;
    const int oy = blockIdx.y;
    const int xbase = blockIdx.x * 256 + cls;
    if (xbase >= HT) return;
#if HAS_TCGEN05
    extern __shared__ char dsm[];
    __shared__ uint32_t s_tmem[1];
    __shared__ unsigned long long s_mbar;

    const int tid = threadIdx.x;
    const int wid = tid >> 5, lid = tid & 31;

    uint32_t dbase = smem_u32(dsm);
    uint32_t abase = (dbase + 1023u) & ~1023u;
    const uint32_t a_s = abase;
    const uint32_t b_s = abase + 16384;
    const uint32_t mbar = smem_u32(&s_mbar);

    if (wid == 0) {
        TCGEN05_ALLOC(smem_u32(&s_tmem[0]), 64);
        TCGEN05_RELINQ();
    }
    if (tid == 0) MBARRIER_INIT(mbar, 1);
    __syncthreads();
    const uint32_t tmem = s_tmem[0];

    const __half* inb = in + (size_t)b * H * W * 64;
    const float* m1b = mask1 + (size_t)b * H * W;

    int phase = 0;
    bool first = true;

#pragma unroll 1
    for (int ky = 0; ky < 3; ky++) {
        if ((oy + ky) & 1) continue;
        const int iy = (oy + ky - 2) >> 1;
        if (iy < 0 || iy >= H) continue;
        const __half* rowp = inb + (size_t)iy * W * 64;
#pragma unroll 1
        for (int kx = 0; kx < 3; kx++) {
            if ((cls + kx) & 1) continue;
            const int ixb = (xbase + kx - 2) >> 1;

            stage_A64h_cp(a_s, tid, rowp, ixb, W);
            stage_B64h_cp(b_s, tid, wH + (ky * 3 + kx) * 4096);
            CP_COMMIT();
            CP_WAIT0();
            FENCE_PROXY_ASYNC();
            __syncthreads();

            if (tid == 0) {
                TCGEN05_FENCE_AFTER();
                uint64_t ad0 = MAKE_DESC(a_s);
                uint64_t bd0 = MAKE_DESC(b_s);
#pragma unroll
                for (int s = 0; s < 4; s++) {
                    unsigned en = (first && s == 0) ? 0u : 1u;
                    TC_MMA_F16(tmem, ad0 + s * 2, bd0 + s * 2, en);
                }
                TCGEN05_COMMIT(mbar);
            }
            first = false;
            MBARRIER_WAIT_PARITY(mbar, phase);
            phase ^= 1;
        }
    }

    TCGEN05_FENCE_AFTER();

    const int m = wid * 32 + lid;
    const int ox = xbase + 2 * m;
    bool valid = (ox < HT);
    float mval = 0.f;
    __half* op = nullptr;
    if (valid) {
#pragma unroll
        for (int ky = 0; ky < 3; ky++) {
            if ((oy + ky) & 1) continue;
            int iy = (oy + ky - 2) >> 1;
            if (iy < 0 || iy >= H) continue;
#pragma unroll
            for (int kx = 0; kx < 3; kx++) {
                if ((cls + kx) & 1) continue;
                int ix = (ox + kx - 2) >> 1;
                if (ix >= 0 && ix < W)
                    mval = fmaxf(mval, m1b[(size_t)iy * W + ix]);
            }
        }
        mval = (mval > 0.f) ? 1.f : 0.f;
        op = out + (((size_t)b * HT + oy) * HT + ox) * 64;
    }
    tc_epi_f16(tmem, bias, mval, op, valid);

    __syncthreads();
    if (wid == 0) TCGEN05_DEALLOC(tmem, 64);
#else
    const int tid = threadIdx.x;
    const int ox = xbase + 2 * tid;
    if (ox >= HT) return;
    const __half* inb = in + (size_t)b * H * W * 64;
    const float* m1b = mask1 + (size_t)b * H * W;
    float acc[64];
#pragma unroll
    for (int c = 0; c < 64; c++) acc[c] = 0.f;
    float mval = 0.f;
    for (int ky = 0; ky < 3; ky++) {
        if ((oy + ky) & 1) continue;
        int iy = (oy + ky - 2) >> 1;
        if (iy < 0 || iy >= H) continue;
        for (int kx = 0; kx < 3; kx++) {
            if ((cls + kx) & 1) continue;
            int ix = (ox + kx - 2) >> 1;
            if (ix < 0 || ix >= W) continue;
            mval = fmaxf(mval, m1b[(size_t)iy * W + ix]);
            const __half* ip = inb + ((size_t)iy * W + ix) * 64;
            const __half* wk = wH + (ky * 3 + kx) * 4096;
            for (int ci = 0; ci < 64; ci++) {
                float iv = __half2float(ip[ci]);
#pragma unroll 16
                for (int co = 0; co < 64; co++)
                    acc[co] = fmaf(iv, __half2float(wk[co * 64 + ci]), acc[co]);
            }
        }
    }
    mval = (mval > 0.f) ? 1.f : 0.f;
    __half* op = out + (((size_t)b * HT + oy) * HT + ox) * 64;
#pragma unroll
    for (int c = 0; c < 64; c++)
        op[c] = __float2half_rn(fmaxf((acc[c] + bias[c]) * mval, 0.f));
#endif
}

// ---------------------------------------------------------------------------
// Launch
// ---------------------------------------------------------------------------
extern "C" void kernel_launch(void* const* d_in, const int* in_sizes, int n_in,
                              void* d_out, int out_size) {
    const float* features = (const float*)d_in[0];
    const int* coors      = (const int*)d_in[1];
    const float* w1 = (const float*)d_in[3];
    const float* b1 = (const float*)d_in[4];
    const float* w2 = (const float*)d_in[5];
    const float* b2 = (const float*)d_in[6];
    const float* w3 = (const float*)d_in[7];
    const float* b3 = (const float*)d_in[8];
    const float* wt = (const float*)d_in[9];
    const float* bt = (const float*)d_in[10];
    const float* w5 = (const float*)d_in[11];
    const float* b5 = (const float*)d_in[12];
    float* out = (float*)d_out;

    const int N = in_sizes[0] / C0;

    float *m1, *wT1;
    __half *x0h, *h1, *h2, *ht, *wH2, *wH3, *wH4, *wH5;
    cudaGetSymbolAddress((void**)&x0h, g_x0h);
    cudaGetSymbolAddress((void**)&m1, g_mask1);
    cudaGetSymbolAddress((void**)&h1, g_h1);
    cudaGetSymbolAddress((void**)&h2, g_h2);
    cudaGetSymbolAddress((void**)&ht, g_ht);
    cudaGetSymbolAddress((void**)&wT1, g_wT1);
    cudaGetSymbolAddress((void**)&wH2, g_wH2);
    cudaGetSymbolAddress((void**)&wH3, g_wH3);
    cudaGetSymbolAddress((void**)&wH4, g_wH4);
    cudaGetSymbolAddress((void**)&wH5, g_wH5);

    const int SMH = 1024 + 16384 + 8192;   // 25600 -> 8 CTAs/SM
    cudaFuncSetAttribute((const void*)conv64h_tc_kernel<true, true>,
                         cudaFuncAttributeMaxDynamicSharedMemorySize, SMH);
    cudaFuncSetAttribute((const void*)conv64h_tc_kernel<false, false>,
                         cudaFuncAttributeMaxDynamicSharedMemorySize, SMH);
    cudaFuncSetAttribute((const void*)conv1_tc_kernel,
                         cudaFuncAttributeMaxDynamicSharedMemorySize, SMH);
    cudaFuncSetAttribute((const void*)convT_tc_kernel,
                         cudaFuncAttributeMaxDynamicSharedMemorySize, SMH);

    {
        dim3 g((9 * 64 * 64 + 255) / 256, 5);
        transposeW_all_kernel<<<g, 256>>>(w2, w3, wt, w5, w1);
    }

    {
        int n8 = BATCH * H * W * C0 / 8;
        zero_kernel<<<(n8 + 255) / 256, 256>>>();
    }
    scatter_kernel<<<(N * 16 + 255) / 256, 256>>>(features, coors, N);
    mask1_kernel<<<(BATCH * H * W + 255) / 256, 256>>>();

    {
        dim3 grid(W / 128, H, BATCH);
        conv1_tc_kernel<<<grid, 128, SMH>>>(x0h, wT1, b1, m1, h1);
        conv64h_tc_kernel<true, true><<<grid, 128, SMH>>>(
            h1, wH2, b2, m1, h2, H, W, H, W, 1);
        conv64h_tc_kernel<true, true><<<grid, 128, SMH>>>(
            h2, wH3, b3, m1, h1, H, W, H, W, 1);
    }
    {
        dim3 grid(3, HT, BATCH * 2);
        convT_tc_kernel<<<grid, 128, SMH>>>(h1, wH4, bt, m1, ht);
    }
    {
        dim3 grid((HO + 127) / 128, HO, BATCH);
        conv64h_tc_kernel<false, false><<<grid, 128, SMH>>>(
            ht, wH5, b5, nullptr, out, HT, HT, HO, HO, 0);
    }
}